// round 8
// baseline (speedup 1.0000x reference)
#include <cuda_runtime.h>
#include <cuda_bf16.h>
#include <math.h>

// ---------------- problem constants ----------------
#define BB 2
#define DIMC 256
#define GG 4
#define CHG 64          // DIM/GROUPS
#define OFFD 128
#define NBG 8           // B*GROUPS
#define FF 4
#define HH 16
#define WW 16
#define PQ 1024         // F*H*W
#define PJ 128          // FD*HD*WD
#define CPB 64
#define INNER 512
#define IT 8            // queries per block in kernel D

// ---------------- scratch ----------------
__device__ float g_q[NBG * OFFD * PQ];
__device__ float g_qT[NBG * PQ * OFFD];   // transposed copy: [bg][p][c]
__device__ float g_grid[NBG * PJ * 3];
__device__ float g_k[NBG * OFFD * PJ];
__device__ float g_v[NBG * OFFD * PJ];
__device__ float g_att[BB * INNER * PQ];

// ---------------- helpers ----------------
__device__ __forceinline__ unsigned long long ffma2(unsigned long long a,
                                                    unsigned long long b,
                                                    unsigned long long c) {
    unsigned long long d;
    asm("fma.rn.f32x2 %0, %1, %2, %3;" : "=l"(d) : "l"(a), "l"(b), "l"(c));
    return d;
}
__device__ __forceinline__ unsigned long long pack2(float lo, float hi) {
    unsigned long long d;
    asm("mov.b64 %0, {%1, %2};" : "=l"(d) : "f"(lo), "f"(hi));
    return d;
}
__device__ __forceinline__ float2 unpack2(unsigned long long v) {
    float2 r;
    asm("mov.b64 {%0, %1}, %2;" : "=f"(r.x), "=f"(r.y) : "l"(v));
    return r;
}
__device__ __forceinline__ void mma16816(float* c, const unsigned* a, const unsigned* b) {
    asm volatile(
        "mma.sync.aligned.m16n8k16.row.col.f32.bf16.bf16.f32 "
        "{%0,%1,%2,%3}, {%4,%5,%6,%7}, {%8,%9}, {%0,%1,%2,%3};"
        : "+f"(c[0]), "+f"(c[1]), "+f"(c[2]), "+f"(c[3])
        : "r"(a[0]), "r"(a[1]), "r"(a[2]), "r"(a[3]), "r"(b[0]), "r"(b[1]));
}
__device__ __forceinline__ unsigned hfma2(unsigned a, unsigned b, unsigned c) {
    unsigned d;
    asm("fma.rn.bf16x2 %0, %1, %2, %3;" : "=r"(d) : "r"(a), "r"(b), "r"(c));
    return d;
}
__device__ __forceinline__ unsigned hadd2(unsigned a, unsigned b) {
    unsigned d;
    asm("add.rn.bf16x2 %0, %1, %2;" : "=r"(d) : "r"(a), "r"(b));
    return d;
}
__device__ __forceinline__ unsigned hmax2z(unsigned a) {
    unsigned d;
    asm("max.bf16x2 %0, %1, %2;" : "=r"(d) : "r"(a), "r"(0u));
    return d;
}
__device__ __forceinline__ unsigned packcvt(float lo, float hi) {
    unsigned d;
    asm("cvt.rn.bf16x2.f32 %0, %1, %2;" : "=r"(d) : "f"(hi), "f"(lo));
    return d;
}
__device__ __forceinline__ unsigned bcastbf(float x) {
    unsigned d;
    asm("cvt.rn.bf16x2.f32 %0, %1, %1;" : "=r"(d) : "f"(x));
    return d;
}

// ============================================================
// Kernel A: grouped 1x1 conv -> q (+ transposed copy g_qT)
// ============================================================
__global__ void k_qproj(const float* __restrict__ x, const float* __restrict__ wq) {
    const int bg = blockIdx.y;
    const int b = bg >> 2, g = bg & 3;
    const int p0 = blockIdx.x * 16;
    const int o = threadIdx.x;

    __shared__ __align__(16) float wqs[CHG * OFFD];   // [i][o]
    __shared__ __align__(16) float xs[CHG * 16];

    const float* wqg = wq + (size_t)g * OFFD * CHG;
    for (int e = o; e < OFFD * CHG; e += 128) {
        int oo = e >> 6, i = e & 63;
        wqs[i * OFFD + oo] = wqg[e];
    }
    for (int e = o; e < CHG * 16; e += 128) {
        int i = e >> 4, p = e & 15;
        xs[e] = x[(size_t)(b * DIMC + g * CHG + i) * PQ + p0 + p];
    }
    __syncthreads();

    unsigned long long acc2[8];
#pragma unroll
    for (int q = 0; q < 8; q++) acc2[q] = 0ull;

#pragma unroll 8
    for (int i = 0; i < CHG; i++) {
        float wv0 = wqs[i * OFFD + o];
        unsigned long long wv = pack2(wv0, wv0);
        const unsigned long long* xr = (const unsigned long long*)(xs + i * 16);
#pragma unroll
        for (int q = 0; q < 8; q++) acc2[q] = ffma2(wv, xr[q], acc2[q]);
    }
    float* qout = g_q + (size_t)(bg * OFFD + o) * PQ + p0;
    float* qtout = g_qT + ((size_t)bg * PQ + p0) * OFFD + o;
#pragma unroll
    for (int q = 0; q < 8; q++) {
        float2 f = unpack2(acc2[q]);
        qout[q * 2 + 0] = f.x;
        qout[q * 2 + 1] = f.y;
        qtout[(q * 2 + 0) * OFFD] = f.x;
        qtout[(q * 2 + 1) * OFFD] = f.y;
    }
}

// ============================================================
// Kernel B: offsets -> deformed grid coords
// ============================================================
__global__ void k_offsets(const float* __restrict__ dww, const float* __restrict__ dwb,
                          const float* __restrict__ pww) {
    const int pos = blockIdx.x;
    const int bg = blockIdx.y;
    const int c = threadIdx.x;
    const int lane = c & 31, wid = c >> 5;

    const int zo = pos >> 6;
    const int yo = (pos >> 3) & 7;
    const int xo = pos & 7;

    __shared__ __align__(16) float dws[64 * OFFD];    // [k][c]
    for (int e = c; e < 64 * OFFD; e += 128) {
        int cc = e >> 6, k = e & 63;
        dws[k * OFFD + cc] = dww[e];
    }
    __syncthreads();

    const float* qT = g_qT + (size_t)bg * PQ * OFFD + c;
    float acc = 0.f;
#pragma unroll
    for (int kz = 0; kz < 4; kz++) {
        int z = 2 * zo - 1 + kz;
        if (z < 0 || z >= FF) continue;
#pragma unroll
        for (int ky = 0; ky < 4; ky++) {
            int y = 2 * yo - 1 + ky;
            if (y < 0 || y >= HH) continue;
#pragma unroll
            for (int kx = 0; kx < 4; kx++) {
                int xx = 2 * xo - 1 + kx;
                if (xx < 0 || xx >= WW) continue;
                int p = (z * HH + y) * WW + xx;
                acc = fmaf(qT[(size_t)p * OFFD],
                           dws[((kz * 4 + ky) * 4 + kx) * OFFD + c], acc);
            }
        }
    }
    float v = acc + dwb[c];
    float act = 0.5f * v * (1.f + erff(v * 0.70710678118654752f));

    __shared__ float acts[OFFD];
    __shared__ float sred[3];
    acts[c] = act;
    __syncthreads();

    if (wid < 3) {
        float s = 0.f;
#pragma unroll
        for (int q = 0; q < 4; q++) {
            int cc = lane + q * 32;
            s = fmaf(acts[cc], pww[wid * OFFD + cc], s);
        }
#pragma unroll
        for (int off = 16; off; off >>= 1) s += __shfl_xor_sync(0xffffffffu, s, off);
        if (lane == 0) sred[wid] = s;
    }
    __syncthreads();

    if (c == 0) {
        float of = tanhf(sred[0]) * 2.0f;
        float oh = tanhf(sred[1]) * 2.0f;
        float ow = tanhf(sred[2]) * 2.0f;
        float gf = 2.0f * ((float)zo + of) / 1.0f - 1.0f;
        float gh = 2.0f * ((float)yo + oh) / 7.0f - 1.0f;
        float gw = 2.0f * ((float)xo + ow) / 7.0f - 1.0f;
        float* gp = g_grid + (size_t)(bg * PJ + pos) * 3;
        gp[0] = gf; gp[1] = gh; gp[2] = gw;
    }
}

// ============================================================
// Kernel C: trilinear grid-sample + k/v projections
// ============================================================
__global__ __launch_bounds__(256)
void k_sample_kv(const float* __restrict__ x, const float* __restrict__ wk,
                 const float* __restrict__ wv) {
    const int bg = blockIdx.x;
    const int jt = blockIdx.y;
    const int b = bg >> 2, g = bg & 3;
    const int tid = threadIdx.x;

    __shared__ __align__(16) float wks[CHG * OFFD];
    __shared__ __align__(16) float wvs[CHG * OFFD];
    __shared__ __align__(16) float kvsS[16 * CHG];

    const float* wkg = wk + (size_t)g * OFFD * CHG;
    const float* wvg = wv + (size_t)g * OFFD * CHG;
    for (int e = tid; e < OFFD * CHG; e += 256) {
        int o = e >> 6, i = e & 63;
        wks[i * OFFD + o] = wkg[e];
        wvs[i * OFFD + o] = wvg[e];
    }

#pragma unroll
    for (int pass = 0; pass < 4; pass++) {
        int jl = pass * 4 + (tid >> 6);
        int ch = tid & 63;
        int j = jt * 16 + jl;
        const float* gp = g_grid + (size_t)(bg * PJ + j) * 3;
        float g0 = gp[0], g1 = gp[1], g2 = gp[2];
        float ix = ((g0 + 1.f) * (float)WW - 1.f) * 0.5f;
        float iy = ((g1 + 1.f) * (float)HH - 1.f) * 0.5f;
        float iz = ((g2 + 1.f) * (float)FF - 1.f) * 0.5f;
        float fx0 = floorf(ix), fy0 = floorf(iy), fz0 = floorf(iz);
        float tx = ix - fx0, ty = iy - fy0, tz = iz - fz0;
        int x0 = (int)fx0, y0 = (int)fy0, z0 = (int)fz0;

        const float* xp = x + (size_t)(b * DIMC + g * CHG + ch) * PQ;
        float acc = 0.f;
#pragma unroll
        for (int dz = 0; dz < 2; dz++)
#pragma unroll
            for (int dy = 0; dy < 2; dy++)
#pragma unroll
                for (int dx = 0; dx < 2; dx++) {
                    int xc = x0 + dx, yc = y0 + dy, zc = z0 + dz;
                    float wgt = (dx ? tx : 1.f - tx) * (dy ? ty : 1.f - ty) *
                                (dz ? tz : 1.f - tz);
                    bool valid = (xc >= 0) & (xc < WW) & (yc >= 0) & (yc < HH) &
                                 (zc >= 0) & (zc < FF);
                    int xi = min(max(xc, 0), WW - 1);
                    int yi = min(max(yc, 0), HH - 1);
                    int zi = min(max(zc, 0), FF - 1);
                    float val = xp[(zi * HH + yi) * WW + xi];
                    acc += valid ? val * wgt : 0.f;
                }
        kvsS[jl * CHG + ch] = acc;
    }
    __syncthreads();

    const int o = tid & 127;
    const int sel = tid >> 7;
    const float* ws = sel ? wvs : wks;
    float* gout = sel ? g_v : g_k;

    float acc[16];
#pragma unroll
    for (int jl = 0; jl < 16; jl++) acc[jl] = 0.f;
#pragma unroll 8
    for (int i = 0; i < CHG; i++) {
        float wv0 = ws[i * OFFD + o];
#pragma unroll
        for (int jl = 0; jl < 16; jl++)
            acc[jl] = fmaf(wv0, kvsS[jl * CHG + i], acc[jl]);
    }
    float* orow = gout + (size_t)(bg * OFFD + o) * PJ + jt * 16;
#pragma unroll
    for (int jl = 0; jl < 16; jl++) orow[jl] = acc[jl];
}

// ============================================================
// Kernel D v7: w1 fragments in SMEM (uint2-packed, conflict-free),
// 3 CTAs/SM, no in-loop shuffles (row sums deferred).
// ============================================================
struct __align__(16) SmemD {
    unsigned w1f[128 * 40];          // [nrow][kt*4+q2] uint2 pairs, stride 20 uint2
    float ts[IT * 3 * PJ];
    float qs[OFFD * IT];
    float attns[IT * 2 * PJ];
    float simS[IT * 2 * PJ];
    uint4 w0p[32];
    float w2s[CPB * 2];
    float b1s[CPB];
    float sumS[16];
};

__global__ __launch_bounds__(256, 3)
void k_attn(const float* __restrict__ cw0, const float* __restrict__ cb0,
            const float* __restrict__ cw1, const float* __restrict__ cb1,
            const float* __restrict__ cw2, const float* __restrict__ cb2) {
    extern __shared__ SmemD smD[];
    SmemD& s = smD[0];

    const int bg = blockIdx.y;
    const int b = bg >> 2, g = bg & 3;
    const int i0 = blockIdx.x * IT;
    const int tid = threadIdx.x;
    const int lane = tid & 31, w = tid >> 5;

    // ---- stage w1 as pre-packed B-fragments ----
    for (int idx = tid; idx < 4096; idx += 256) {
        int nrow = idx >> 5, rr = idx & 31;
        int kt = rr >> 3, q2p = (rr >> 1) & 3, wv = rr & 1;
        int k = kt * 16 + q2p * 2 + wv * 8;
        s.w1f[nrow * 40 + (kt * 4 + q2p) * 2 + wv] =
            packcvt(cw1[k * 64 + nrow], cw1[(k + 1) * 64 + nrow]);
    }
    if (tid < 32) {
        int c = tid * 2;
        uint4 wp;
        wp.x = packcvt(cw0[c], cw0[c + 1]);
        wp.y = packcvt(cw0[64 + c], cw0[64 + c + 1]);
        wp.z = packcvt(cw0[128 + c], cw0[128 + c + 1]);
        wp.w = packcvt(cb0[c], cb0[c + 1]);
        s.w0p[tid] = wp;
    }
    if (tid >= 64 && tid < 192) s.w2s[tid - 64] = cw2[tid - 64];
    if (tid >= 192) s.b1s[tid - 192] = cb1[tid - 192];
    {
        int o = tid >> 1, half = (tid & 1) * 4;
        float4 qv = *(const float4*)(g_q + (size_t)(bg * OFFD + o) * PQ + i0 + half);
        s.qs[o * IT + half + 0] = qv.x * 0.125f;
        s.qs[o * IT + half + 1] = qv.y * 0.125f;
        s.qs[o * IT + half + 2] = qv.z * 0.125f;
        s.qs[o * IT + half + 3] = qv.w * 0.125f;
    }
    for (int e = tid; e < IT * 3 * PJ; e += 256) {
        int q = e / 384, rem = e - q * 384;
        int d = rem >> 7, j = rem & 127;
        int i = i0 + q;
        float gq;
        if (d == 0) gq = 2.0f * (float)(i >> 8) / 3.0f - 1.0f;
        else if (d == 1) gq = 2.0f * (float)((i >> 4) & 15) / 15.0f - 1.0f;
        else gq = 2.0f * (float)(i & 15) / 15.0f - 1.0f;
        float gj = g_grid[(size_t)(bg * PJ + j) * 3 + d];
        float p = gq - gj;
        s.ts[e] = copysignf(log1pf(fabsf(p)), p);
    }
    __syncthreads();                                     // barrier 1

    const int r = w * 16 + (lane >> 2);
    const int q2 = lane & 3;
    const int nl = lane >> 2;

    // layer2 fragments + b1 packs (small, register-resident)
    unsigned bw2[4][2], b1p[4][2];
#pragma unroll
    for (int kt2 = 0; kt2 < 4; kt2++) {
        int k0 = kt2 * 16 + q2 * 2;
        bw2[kt2][0] = (nl < 2) ? packcvt(s.w2s[k0 * 2 + nl], s.w2s[(k0 + 1) * 2 + nl]) : 0u;
        bw2[kt2][1] = (nl < 2) ? packcvt(s.w2s[(k0 + 8) * 2 + nl], s.w2s[(k0 + 9) * 2 + nl]) : 0u;
        b1p[kt2][0] = packcvt(s.b1s[k0], s.b1s[k0 + 1]);
        b1p[kt2][1] = packcvt(s.b1s[k0 + 8], s.b1s[k0 + 9]);
    }

    // ---- sim -> smem (j-owner layout), f32x2 ----
    {
        const int jj = tid & 127, eh = tid >> 7;
        unsigned long long sim2[4] = {0ull, 0ull, 0ull, 0ull};
        const float* kb = g_k + (size_t)bg * OFFD * PJ + (size_t)eh * 64 * PJ + jj;
#pragma unroll 4
        for (int o = 0; o < 64; o++) {
            float kv = kb[o * PJ];
            unsigned long long kvp = pack2(kv, kv);
            const unsigned long long* qp =
                (const unsigned long long*)(s.qs + (eh * 64 + o) * IT);
            sim2[0] = ffma2(qp[0], kvp, sim2[0]);
            sim2[1] = ffma2(qp[1], kvp, sim2[1]);
            sim2[2] = ffma2(qp[2], kvp, sim2[2]);
            sim2[3] = ffma2(qp[3], kvp, sim2[3]);
        }
#pragma unroll
        for (int h2 = 0; h2 < 4; h2++) {
            float2 f = unpack2(sim2[h2]);
            s.simS[((2 * h2 + 0) * 2 + eh) * PJ + jj] = f.x;
            s.simS[((2 * h2 + 1) * 2 + eh) * PJ + jj] = f.y;
        }
    }
    __syncthreads();                                     // barrier 2

    // ---- per-query loop (no block barriers, no shuffles) ----
    for (int t = 0; t < IT; t++) {
        const float* tq = s.ts + t * 3 * PJ;
        unsigned tp0[3], tp1[3];
#pragma unroll
        for (int d = 0; d < 3; d++) {
            tp0[d] = bcastbf(tq[d * PJ + r]);
            tp1[d] = bcastbf(tq[d * PJ + r + 8]);
        }

        unsigned ah[16];
#pragma unroll
        for (int kt = 0; kt < 4; kt++) {
#pragma unroll
            for (int cp = 0; cp < 2; cp++) {
                uint4 W = s.w0p[kt * 8 + q2 + cp * 4];
                ah[kt * 4 + cp * 2 + 0] =
                    hmax2z(hfma2(tp0[0], W.x, hfma2(tp0[1], W.y, hfma2(tp0[2], W.z, W.w))));
                ah[kt * 4 + cp * 2 + 1] =
                    hmax2z(hfma2(tp1[0], W.x, hfma2(tp1[1], W.y, hfma2(tp1[2], W.z, W.w))));
            }
        }

        float acc2[4] = {0.f, 0.f, 0.f, 0.f};
#pragma unroll
        for (int kt2 = 0; kt2 < 4; kt2++) {
            float accA[4] = {0.f, 0.f, 0.f, 0.f};
            float accB[4] = {0.f, 0.f, 0.f, 0.f};
            int rowA = (2 * kt2) * 8 + nl;        // nf = 2*kt2
            int rowB = (2 * kt2 + 1) * 8 + nl;    // nf = 2*kt2+1
#pragma unroll
            for (int kt = 0; kt < 4; kt++) {
                uint2 fA = *(const uint2*)&s.w1f[rowA * 40 + (kt * 4 + q2) * 2];
                uint2 fB = *(const uint2*)&s.w1f[rowB * 40 + (kt * 4 + q2) * 2];
                unsigned bA[2] = {fA.x, fA.y};
                unsigned bB[2] = {fB.x, fB.y};
                mma16816(accA, &ah[kt * 4], bA);
                mma16816(accB, &ah[kt * 4], bB);
            }
            unsigned a2[4];
            a2[0] = hmax2z(hadd2(packcvt(accA[0], accA[1]), b1p[kt2][0]));
            a2[1] = hmax2z(hadd2(packcvt(accA[2], accA[3]), b1p[kt2][0]));
            a2[2] = hmax2z(hadd2(packcvt(accB[0], accB[1]), b1p[kt2][1]));
            a2[3] = hmax2z(hadd2(packcvt(accB[2], accB[3]), b1p[kt2][1]));
            mma16816(acc2, a2, bw2[kt2]);
        }

        if (q2 == 0) {
            s.attns[(t * 2 + 0) * PJ + r] = __expf(s.simS[(t * 2 + 0) * PJ + r] + acc2[0]);
            s.attns[(t * 2 + 1) * PJ + r] = __expf(s.simS[(t * 2 + 1) * PJ + r] + acc2[1]);
            s.attns[(t * 2 + 0) * PJ + r + 8] = __expf(s.simS[(t * 2 + 0) * PJ + r + 8] + acc2[2]);
            s.attns[(t * 2 + 1) * PJ + r + 8] = __expf(s.simS[(t * 2 + 1) * PJ + r + 8] + acc2[3]);
        }
    }
    __syncthreads();                                     // barrier 3

    // ---- row sums (16 groups of 16 threads, one pass) ----
    {
        int p16 = tid >> 4;            // = t*2 + head
        int l16 = tid & 15;
        const float4* ar = (const float4*)(s.attns + p16 * PJ);
        float4 a0 = ar[l16 * 2], a1 = ar[l16 * 2 + 1];
        float ps = ((a0.x + a0.y) + (a0.z + a0.w)) + ((a1.x + a1.y) + (a1.z + a1.w));
        ps += __shfl_xor_sync(0xffffffffu, ps, 1);
        ps += __shfl_xor_sync(0xffffffffu, ps, 2);
        ps += __shfl_xor_sync(0xffffffffu, ps, 4);
        ps += __shfl_xor_sync(0xffffffffu, ps, 8);
        if (l16 == 0) s.sumS[p16] = ps;
    }
    __syncthreads();                                     // barrier 4

    // ---- attn @ V with deferred normalization ----
    {
        const int o = tid & 127, qh = tid >> 7, e = o >> 6;
        const ulonglong2* vrow = (const ulonglong2*)(g_v + (size_t)(bg * OFFD + o) * PJ);
        for (int t = qh * 4; t < qh * 4 + 4; t++) {
            float S = s.sumS[t * 2 + e];
            const ulonglong2* arow = (const ulonglong2*)(s.attns + (t * 2 + e) * PJ);
            unsigned long long accA = 0ull, accB = 0ull;
#pragma unroll
            for (int q = 0; q < 32; q++) {
                ulonglong2 av = arow[q];
                ulonglong2 vv = vrow[q];
                accA = ffma2(av.x, vv.x, accA);
                accB = ffma2(av.y, vv.y, accB);
            }
            float2 fa = unpack2(accA), fb = unpack2(accB);
            g_att[(size_t)(b * INNER + g * OFFD + o) * PQ + i0 + t] =
                (fa.x + fa.y + fb.x + fb.y) / S;
        }
    }
}

// ============================================================
// Kernel E: output projection (f32x2 packed inner product)
// ============================================================
__global__ void k_oproj(const float* __restrict__ wo, const float* __restrict__ bo,
                        float* __restrict__ out) {
    const int p0 = blockIdx.x * 64;
    const int o0 = blockIdx.y * 64;
    const int b = blockIdx.z;
    const int tid = threadIdx.x;
    const int tx = tid & 15, ty = tid >> 4;

    __shared__ __align__(16) float As[16 * 64];
    __shared__ __align__(16) float Bs[16 * 64];

    unsigned long long acc2[4][2];
#pragma unroll
    for (int a = 0; a < 4; a++) { acc2[a][0] = 0ull; acc2[a][1] = 0ull; }

    for (int k0 = 0; k0 < INNER; k0 += 16) {
        {
            int m = tid >> 2, kqq = (tid & 3) * 4;
            float4 wv = *(const float4*)(wo + (size_t)(o0 + m) * INNER + k0 + kqq);
            As[(kqq + 0) * 64 + m] = wv.x;
            As[(kqq + 1) * 64 + m] = wv.y;
            As[(kqq + 2) * 64 + m] = wv.z;
            As[(kqq + 3) * 64 + m] = wv.w;
            int k = tid >> 4, pq = (tid & 15) * 4;
            float4 bv = *(const float4*)(g_att + (size_t)(b * INNER + k0 + k) * PQ + p0 + pq);
            *(float4*)(Bs + k * 64 + pq) = bv;
        }
        __syncthreads();
#pragma unroll
        for (int k = 0; k < 16; k++) {
            float4 am = *(const float4*)(As + k * 64 + ty * 4);
            const unsigned long long* bn =
                (const unsigned long long*)(Bs + k * 64 + tx * 4);
            unsigned long long b0 = bn[0], b1 = bn[1];
            unsigned long long a0 = pack2(am.x, am.x);
            unsigned long long a1 = pack2(am.y, am.y);
            unsigned long long a2 = pack2(am.z, am.z);
            unsigned long long a3 = pack2(am.w, am.w);
            acc2[0][0] = ffma2(a0, b0, acc2[0][0]); acc2[0][1] = ffma2(a0, b1, acc2[0][1]);
            acc2[1][0] = ffma2(a1, b0, acc2[1][0]); acc2[1][1] = ffma2(a1, b1, acc2[1][1]);
            acc2[2][0] = ffma2(a2, b0, acc2[2][0]); acc2[2][1] = ffma2(a2, b1, acc2[2][1]);
            acc2[3][0] = ffma2(a3, b0, acc2[3][0]); acc2[3][1] = ffma2(a3, b1, acc2[3][1]);
        }
        __syncthreads();
    }
#pragma unroll
    for (int a = 0; a < 4; a++) {
        float bias = bo[o0 + ty * 4 + a];
        float2 c0 = unpack2(acc2[a][0]);
        float2 c1 = unpack2(acc2[a][1]);
        float* op = out + (size_t)(b * DIMC + o0 + ty * 4 + a) * PQ + p0 + tx * 4;
        op[0] = c0.x + bias;
        op[1] = c0.y + bias;
        op[2] = c1.x + bias;
        op[3] = c1.y + bias;
    }
}

// ============================================================
extern "C" void kernel_launch(void* const* d_in, const int* in_sizes, int n_in,
                              void* d_out, int out_size) {
    const float* x    = (const float*)d_in[0];
    const float* wq   = (const float*)d_in[1];
    const float* wk   = (const float*)d_in[2];
    const float* wv   = (const float*)d_in[3];
    const float* dww  = (const float*)d_in[4];
    const float* dwb  = (const float*)d_in[5];
    const float* pww  = (const float*)d_in[6];
    const float* cw0  = (const float*)d_in[7];
    const float* cb0  = (const float*)d_in[8];
    const float* cw1  = (const float*)d_in[9];
    const float* cb1  = (const float*)d_in[10];
    const float* cw2  = (const float*)d_in[11];
    const float* cb2  = (const float*)d_in[12];
    const float* wo   = (const float*)d_in[13];
    const float* bo   = (const float*)d_in[14];
    float* out = (float*)d_out;
    (void)cb2; // per-head constant bias cancels in softmax

    cudaFuncSetAttribute(k_attn, cudaFuncAttributeMaxDynamicSharedMemorySize,
                         (int)sizeof(SmemD));

    k_qproj<<<dim3(PQ / 16, NBG), 128>>>(x, wq);
    k_offsets<<<dim3(PJ, NBG), 128>>>(dww, dwb, pww);
    k_sample_kv<<<dim3(NBG, PJ / 16), 256>>>(x, wk, wv);
    k_attn<<<dim3(PQ / IT, NBG), 256, sizeof(SmemD)>>>(cw0, cb0, cw1, cb1, cw2, cb2);
    k_oproj<<<dim3(PQ / 64, DIMC / 64, BB), 256>>>(wo, bo, out);
}

// round 10
// speedup vs baseline: 1.2207x; 1.2207x over previous
#include <cuda_runtime.h>
#include <cuda_bf16.h>
#include <math.h>

// ---------------- problem constants ----------------
#define BB 2
#define DIMC 256
#define GG 4
#define CHG 64          // DIM/GROUPS
#define OFFD 128
#define NBG 8           // B*GROUPS
#define FF 4
#define HH 16
#define WW 16
#define PQ 1024         // F*H*W
#define PJ 128          // FD*HD*WD
#define CPB 64
#define INNER 512
#define IT 16           // queries per block in kernel D
#define KP 66           // padded K stride (halves) for w1 smem

// ---------------- scratch ----------------
__device__ float g_q[NBG * OFFD * PQ];
__device__ float g_qT[NBG * PQ * OFFD];   // transposed copy: [bg][p][c]
__device__ float g_grid[NBG * PJ * 3];
__device__ float g_t[NBG * 3 * 16 * PJ];  // sign-log table [bg][d][v][j]
__device__ float g_k[NBG * OFFD * PJ];
__device__ float g_v[NBG * OFFD * PJ];
__device__ float g_att[BB * INNER * PQ];

// ---------------- helpers ----------------
__device__ __forceinline__ unsigned long long ffma2(unsigned long long a,
                                                    unsigned long long b,
                                                    unsigned long long c) {
    unsigned long long d;
    asm("fma.rn.f32x2 %0, %1, %2, %3;" : "=l"(d) : "l"(a), "l"(b), "l"(c));
    return d;
}
__device__ __forceinline__ unsigned long long pack2(float lo, float hi) {
    unsigned long long d;
    asm("mov.b64 %0, {%1, %2};" : "=l"(d) : "f"(lo), "f"(hi));
    return d;
}
__device__ __forceinline__ float2 unpack2(unsigned long long v) {
    float2 r;
    asm("mov.b64 {%0, %1}, %2;" : "=f"(r.x), "=f"(r.y) : "l"(v));
    return r;
}
__device__ __forceinline__ void mma16816(float* c, const unsigned* a, const unsigned* b) {
    asm volatile(
        "mma.sync.aligned.m16n8k16.row.col.f32.bf16.bf16.f32 "
        "{%0,%1,%2,%3}, {%4,%5,%6,%7}, {%8,%9}, {%0,%1,%2,%3};"
        : "+f"(c[0]), "+f"(c[1]), "+f"(c[2]), "+f"(c[3])
        : "r"(a[0]), "r"(a[1]), "r"(a[2]), "r"(a[3]), "r"(b[0]), "r"(b[1]));
}
__device__ __forceinline__ unsigned hfma2(unsigned a, unsigned b, unsigned c) {
    unsigned d;
    asm("fma.rn.bf16x2 %0, %1, %2, %3;" : "=r"(d) : "r"(a), "r"(b), "r"(c));
    return d;
}
__device__ __forceinline__ unsigned hadd2(unsigned a, unsigned b) {
    unsigned d;
    asm("add.rn.bf16x2 %0, %1, %2;" : "=r"(d) : "r"(a), "r"(b));
    return d;
}
__device__ __forceinline__ unsigned hmax2z(unsigned a) {
    unsigned d;
    asm("max.bf16x2 %0, %1, %2;" : "=r"(d) : "r"(a), "r"(0u));
    return d;
}
__device__ __forceinline__ unsigned packcvt(float lo, float hi) {
    unsigned d;
    asm("cvt.rn.bf16x2.f32 %0, %1, %2;" : "=r"(d) : "f"(hi), "f"(lo));
    return d;
}
__device__ __forceinline__ unsigned bcastbf(float x) {
    unsigned d;
    asm("cvt.rn.bf16x2.f32 %0, %1, %1;" : "=r"(d) : "f"(x));
    return d;
}

// ============================================================
// Kernel A: grouped 1x1 conv -> q (+ transposed copy g_qT)
// ============================================================
__global__ void k_qproj(const float* __restrict__ x, const float* __restrict__ wq) {
    const int bg = blockIdx.y;
    const int b = bg >> 2, g = bg & 3;
    const int p0 = blockIdx.x * 16;
    const int o = threadIdx.x;

    __shared__ __align__(16) float wqs[CHG * OFFD];   // [i][o]
    __shared__ __align__(16) float xs[CHG * 16];

    const float* wqg = wq + (size_t)g * OFFD * CHG;
    for (int e = o; e < OFFD * CHG; e += 128) {
        int oo = e >> 6, i = e & 63;
        wqs[i * OFFD + oo] = wqg[e];
    }
    for (int e = o; e < CHG * 16; e += 128) {
        int i = e >> 4, p = e & 15;
        xs[e] = x[(size_t)(b * DIMC + g * CHG + i) * PQ + p0 + p];
    }
    __syncthreads();

    unsigned long long acc2[8];
#pragma unroll
    for (int q = 0; q < 8; q++) acc2[q] = 0ull;

#pragma unroll 8
    for (int i = 0; i < CHG; i++) {
        float wv0 = wqs[i * OFFD + o];
        unsigned long long wv = pack2(wv0, wv0);
        const unsigned long long* xr = (const unsigned long long*)(xs + i * 16);
#pragma unroll
        for (int q = 0; q < 8; q++) acc2[q] = ffma2(wv, xr[q], acc2[q]);
    }
    float* qout = g_q + (size_t)(bg * OFFD + o) * PQ + p0;
    float* qtout = g_qT + ((size_t)bg * PQ + p0) * OFFD + o;
#pragma unroll
    for (int q = 0; q < 8; q++) {
        float2 f = unpack2(acc2[q]);
        qout[q * 2 + 0] = f.x;
        qout[q * 2 + 1] = f.y;
        qtout[(q * 2 + 0) * OFFD] = f.x;
        qtout[(q * 2 + 1) * OFFD] = f.y;
    }
}

// ============================================================
// Kernel B: offsets -> grid coords + sign-log lookup table
// ============================================================
__global__ void k_offsets(const float* __restrict__ dww, const float* __restrict__ dwb,
                          const float* __restrict__ pww) {
    const int pos = blockIdx.x;
    const int bg = blockIdx.y;
    const int c = threadIdx.x;
    const int lane = c & 31, wid = c >> 5;

    const int zo = pos >> 6;
    const int yo = (pos >> 3) & 7;
    const int xo = pos & 7;

    __shared__ __align__(16) float dws[64 * OFFD];    // [k][c]
    for (int e = c; e < 64 * OFFD; e += 128) {
        int cc = e >> 6, k = e & 63;
        dws[k * OFFD + cc] = dww[e];
    }
    __syncthreads();

    const float* qT = g_qT + (size_t)bg * PQ * OFFD + c;
    float acc = 0.f;
#pragma unroll
    for (int kz = 0; kz < 4; kz++) {
        int z = 2 * zo - 1 + kz;
        if (z < 0 || z >= FF) continue;
#pragma unroll
        for (int ky = 0; ky < 4; ky++) {
            int y = 2 * yo - 1 + ky;
            if (y < 0 || y >= HH) continue;
#pragma unroll
            for (int kx = 0; kx < 4; kx++) {
                int xx = 2 * xo - 1 + kx;
                if (xx < 0 || xx >= WW) continue;
                int p = (z * HH + y) * WW + xx;
                acc = fmaf(qT[(size_t)p * OFFD],
                           dws[((kz * 4 + ky) * 4 + kx) * OFFD + c], acc);
            }
        }
    }
    float v = acc + dwb[c];
    float act = 0.5f * v * (1.f + erff(v * 0.70710678118654752f));

    __shared__ float acts[OFFD];
    __shared__ float sred[3];
    __shared__ float gcoord[3];
    acts[c] = act;
    __syncthreads();

    if (wid < 3) {
        float s = 0.f;
#pragma unroll
        for (int q = 0; q < 4; q++) {
            int cc = lane + q * 32;
            s = fmaf(acts[cc], pww[wid * OFFD + cc], s);
        }
#pragma unroll
        for (int off = 16; off; off >>= 1) s += __shfl_xor_sync(0xffffffffu, s, off);
        if (lane == 0) sred[wid] = s;
    }
    __syncthreads();

    if (c == 0) {
        float of = tanhf(sred[0]) * 2.0f;
        float oh = tanhf(sred[1]) * 2.0f;
        float ow = tanhf(sred[2]) * 2.0f;
        float gf = 2.0f * ((float)zo + of) / 1.0f - 1.0f;
        float gh = 2.0f * ((float)yo + oh) / 7.0f - 1.0f;
        float gw = 2.0f * ((float)xo + ow) / 7.0f - 1.0f;
        float* gp = g_grid + (size_t)(bg * PJ + pos) * 3;
        gp[0] = gf; gp[1] = gh; gp[2] = gw;
        gcoord[0] = gf; gcoord[1] = gh; gcoord[2] = gw;
    }
    __syncthreads();

    // sign-log table: only 4+16+16 distinct query coords per (bg,j)
    if (c < 36) {
        int d = (c < 4) ? 0 : ((c < 20) ? 1 : 2);
        int vq = (c < 4) ? c : ((c < 20) ? c - 4 : c - 20);
        float denom = (d == 0) ? 3.0f : 15.0f;
        float gq = 2.0f * (float)vq / denom - 1.0f;
        float p = gq - gcoord[d];
        g_t[(((size_t)bg * 3 + d) * 16 + vq) * PJ + pos] =
            copysignf(log1pf(fabsf(p)), p);
    }
}

// ============================================================
// Kernel C: trilinear grid-sample + k/v projections
// ============================================================
__global__ __launch_bounds__(256)
void k_sample_kv(const float* __restrict__ x, const float* __restrict__ wk,
                 const float* __restrict__ wv) {
    const int bg = blockIdx.x;
    const int jt = blockIdx.y;
    const int b = bg >> 2, g = bg & 3;
    const int tid = threadIdx.x;

    __shared__ __align__(16) float wks[CHG * OFFD];
    __shared__ __align__(16) float wvs[CHG * OFFD];
    __shared__ __align__(16) float kvsS[16 * CHG];

    const float* wkg = wk + (size_t)g * OFFD * CHG;
    const float* wvg = wv + (size_t)g * OFFD * CHG;
    for (int e = tid; e < OFFD * CHG; e += 256) {
        int o = e >> 6, i = e & 63;
        wks[i * OFFD + o] = wkg[e];
        wvs[i * OFFD + o] = wvg[e];
    }

#pragma unroll
    for (int pass = 0; pass < 4; pass++) {
        int jl = pass * 4 + (tid >> 6);
        int ch = tid & 63;
        int j = jt * 16 + jl;
        const float* gp = g_grid + (size_t)(bg * PJ + j) * 3;
        float g0 = gp[0], g1 = gp[1], g2 = gp[2];
        float ix = ((g0 + 1.f) * (float)WW - 1.f) * 0.5f;
        float iy = ((g1 + 1.f) * (float)HH - 1.f) * 0.5f;
        float iz = ((g2 + 1.f) * (float)FF - 1.f) * 0.5f;
        float fx0 = floorf(ix), fy0 = floorf(iy), fz0 = floorf(iz);
        float tx = ix - fx0, ty = iy - fy0, tz = iz - fz0;
        int x0 = (int)fx0, y0 = (int)fy0, z0 = (int)fz0;

        const float* xp = x + (size_t)(b * DIMC + g * CHG + ch) * PQ;
        float acc = 0.f;
#pragma unroll
        for (int dz = 0; dz < 2; dz++)
#pragma unroll
            for (int dy = 0; dy < 2; dy++)
#pragma unroll
                for (int dx = 0; dx < 2; dx++) {
                    int xc = x0 + dx, yc = y0 + dy, zc = z0 + dz;
                    float wgt = (dx ? tx : 1.f - tx) * (dy ? ty : 1.f - ty) *
                                (dz ? tz : 1.f - tz);
                    bool valid = (xc >= 0) & (xc < WW) & (yc >= 0) & (yc < HH) &
                                 (zc >= 0) & (zc < FF);
                    int xi = min(max(xc, 0), WW - 1);
                    int yi = min(max(yc, 0), HH - 1);
                    int zi = min(max(zc, 0), FF - 1);
                    float val = xp[(zi * HH + yi) * WW + xi];
                    acc += valid ? val * wgt : 0.f;
                }
        kvsS[jl * CHG + ch] = acc;
    }
    __syncthreads();

    const int o = tid & 127;
    const int sel = tid >> 7;
    const float* ws = sel ? wvs : wks;
    float* gout = sel ? g_v : g_k;

    float acc[16];
#pragma unroll
    for (int jl = 0; jl < 16; jl++) acc[jl] = 0.f;
#pragma unroll 8
    for (int i = 0; i < CHG; i++) {
        float wv0 = ws[i * OFFD + o];
#pragma unroll
        for (int jl = 0; jl < 16; jl++)
            acc[jl] = fmaf(wv0, kvsS[jl * CHG + i], acc[jl]);
    }
    float* orow = gout + (size_t)(bg * OFFD + o) * PJ + jt * 16;
#pragma unroll
    for (int jl = 0; jl < 16; jl++) orow[jl] = acc[jl];
}

// ============================================================
// Kernel D v8: v6 core (register B-frags, 2 CTAs) + IT=16,
// sign-log lookups, and batched deferred exp (MUFU relief).
// ============================================================
struct __align__(16) SmemD {
    __nv_bfloat16 w1h[CPB * KP];     // 8448 B
    float ts[IT * 3 * PJ];           // 24576 B
    float qs[OFFD * IT];             // 8192 B
    float attns[IT * 2 * PJ];        // 16384 B (logits, then exp)
    float simS[IT * 2 * PJ];         // 16384 B
    uint4 w0p[32];
    float w2s[CPB * 2];
    float b1s[CPB];
    float sumS[IT * 2];
};

__global__ __launch_bounds__(256, 2)
void k_attn(const float* __restrict__ cw0, const float* __restrict__ cb0,
            const float* __restrict__ cw1, const float* __restrict__ cb1,
            const float* __restrict__ cw2, const float* __restrict__ cb2) {
    extern __shared__ SmemD smD[];
    SmemD& s = smD[0];

    const int bg = blockIdx.y;
    const int b = bg >> 2, g = bg & 3;
    const int i0 = blockIdx.x * IT;
    const int tid = threadIdx.x;
    const int lane = tid & 31, w = tid >> 5;

    // ---- stage ----
    for (int e = tid; e < CPB * CPB; e += 256) {
        int k = e >> 6, n = e & 63;
        s.w1h[n * KP + k] = __float2bfloat16_rn(cw1[e]);
    }
    if (tid < 32) {
        int c = tid * 2;
        uint4 wp;
        wp.x = packcvt(cw0[c], cw0[c + 1]);
        wp.y = packcvt(cw0[64 + c], cw0[64 + c + 1]);
        wp.z = packcvt(cw0[128 + c], cw0[128 + c + 1]);
        wp.w = packcvt(cb0[c], cb0[c + 1]);
        s.w0p[tid] = wp;
    }
    if (tid >= 64 && tid < 192) s.w2s[tid - 64] = cw2[tid - 64];
    if (tid >= 192) s.b1s[tid - 192] = cb1[tid - 192];
    {
        int o = tid >> 1, half = (tid & 1) * 8;
        const float* qp = g_q + (size_t)(bg * OFFD + o) * PQ + i0 + half;
        float4 qv0 = *(const float4*)qp;
        float4 qv1 = *(const float4*)(qp + 4);
        s.qs[o * IT + half + 0] = qv0.x * 0.125f;
        s.qs[o * IT + half + 1] = qv0.y * 0.125f;
        s.qs[o * IT + half + 2] = qv0.z * 0.125f;
        s.qs[o * IT + half + 3] = qv0.w * 0.125f;
        s.qs[o * IT + half + 4] = qv1.x * 0.125f;
        s.qs[o * IT + half + 5] = qv1.y * 0.125f;
        s.qs[o * IT + half + 6] = qv1.z * 0.125f;
        s.qs[o * IT + half + 7] = qv1.w * 0.125f;
    }
    // sign-log table lookups (no MUFU)
    for (int e = tid; e < IT * 3 * PJ; e += 256) {
        int q = e / 384, rem = e - q * 384;
        int d = rem >> 7, j = rem & 127;
        int i = i0 + q;
        int vq = (d == 0) ? (i >> 8) : ((d == 1) ? ((i >> 4) & 15) : (i & 15));
        s.ts[e] = g_t[(((size_t)bg * 3 + d) * 16 + vq) * PJ + j];
    }
    __syncthreads();                                     // barrier 1

    const int r = w * 16 + (lane >> 2);
    const int q2 = lane & 3;
    const int kq = q2 * 2;
    const int nl = lane >> 2;

    // ---- hoist w1 B-fragments into registers (query-invariant) ----
    unsigned bfr[8][4][2];
#pragma unroll
    for (int nf = 0; nf < 8; nf++) {
        int nrow = nf * 8 + nl;
#pragma unroll
        for (int kt = 0; kt < 4; kt++) {
            bfr[nf][kt][0] = *(const unsigned*)&s.w1h[nrow * KP + kt * 16 + kq];
            bfr[nf][kt][1] = *(const unsigned*)&s.w1h[nrow * KP + kt * 16 + kq + 8];
        }
    }
    // layer2 fragments + b1 packs
    unsigned bw2[4][2], b1p[4][2];
#pragma unroll
    for (int kt2 = 0; kt2 < 4; kt2++) {
        int k0 = kt2 * 16 + kq;
        bw2[kt2][0] = (nl < 2) ? packcvt(s.w2s[k0 * 2 + nl], s.w2s[(k0 + 1) * 2 + nl]) : 0u;
        bw2[kt2][1] = (nl < 2) ? packcvt(s.w2s[(k0 + 8) * 2 + nl], s.w2s[(k0 + 9) * 2 + nl]) : 0u;
        b1p[kt2][0] = packcvt(s.b1s[k0], s.b1s[k0 + 1]);
        b1p[kt2][1] = packcvt(s.b1s[k0 + 8], s.b1s[k0 + 9]);
    }

    // ---- sim -> smem (j-owner layout), f32x2, 16 queries ----
    {
        const int jj = tid & 127, eh = tid >> 7;
        unsigned long long sim2[8];
#pragma unroll
        for (int h = 0; h < 8; h++) sim2[h] = 0ull;
        const float* kb = g_k + (size_t)bg * OFFD * PJ + (size_t)eh * 64 * PJ + jj;
#pragma unroll 4
        for (int o = 0; o < 64; o++) {
            float kv = kb[o * PJ];
            unsigned long long kvp = pack2(kv, kv);
            const unsigned long long* qp =
                (const unsigned long long*)(s.qs + (eh * 64 + o) * IT);
#pragma unroll
            for (int h = 0; h < 8; h++) sim2[h] = ffma2(qp[h], kvp, sim2[h]);
        }
#pragma unroll
        for (int h = 0; h < 8; h++) {
            float2 f = unpack2(sim2[h]);
            s.simS[((2 * h + 0) * 2 + eh) * PJ + jj] = f.x;
            s.simS[((2 * h + 1) * 2 + eh) * PJ + jj] = f.y;
        }
    }
    __syncthreads();                                     // barrier 2

    // ---- per-query loop: logits only (no exp, no shuffles) ----
    for (int t = 0; t < IT; t++) {
        const float* tq = s.ts + t * 3 * PJ;
        unsigned tp0[3], tp1[3];
#pragma unroll
        for (int d = 0; d < 3; d++) {
            tp0[d] = bcastbf(tq[d * PJ + r]);
            tp1[d] = bcastbf(tq[d * PJ + r + 8]);
        }

        unsigned ah[16];
#pragma unroll
        for (int kt = 0; kt < 4; kt++) {
#pragma unroll
            for (int cp = 0; cp < 2; cp++) {
                uint4 W = s.w0p[kt * 8 + q2 + cp * 4];
                ah[kt * 4 + cp * 2 + 0] =
                    hmax2z(hfma2(tp0[0], W.x, hfma2(tp0[1], W.y, hfma2(tp0[2], W.z, W.w))));
                ah[kt * 4 + cp * 2 + 1] =
                    hmax2z(hfma2(tp1[0], W.x, hfma2(tp1[1], W.y, hfma2(tp1[2], W.z, W.w))));
            }
        }

        float acc2[4] = {0.f, 0.f, 0.f, 0.f};
#pragma unroll
        for (int kt2 = 0; kt2 < 4; kt2++) {
            float accA[4] = {0.f, 0.f, 0.f, 0.f};
            float accB[4] = {0.f, 0.f, 0.f, 0.f};
#pragma unroll
            for (int kt = 0; kt < 4; kt++) {
                mma16816(accA, &ah[kt * 4], bfr[2 * kt2][kt]);
                mma16816(accB, &ah[kt * 4], bfr[2 * kt2 + 1][kt]);
            }
            unsigned a2[4];
            a2[0] = hmax2z(hadd2(packcvt(accA[0], accA[1]), b1p[kt2][0]));
            a2[1] = hmax2z(hadd2(packcvt(accA[2], accA[3]), b1p[kt2][0]));
            a2[2] = hmax2z(hadd2(packcvt(accB[0], accB[1]), b1p[kt2][1]));
            a2[3] = hmax2z(hadd2(packcvt(accB[2], accB[3]), b1p[kt2][1]));
            mma16816(acc2, a2, bw2[kt2]);
        }

        if (q2 == 0) {
            s.attns[(t * 2 + 0) * PJ + r]     = s.simS[(t * 2 + 0) * PJ + r] + acc2[0];
            s.attns[(t * 2 + 1) * PJ + r]     = s.simS[(t * 2 + 1) * PJ + r] + acc2[1];
            s.attns[(t * 2 + 0) * PJ + r + 8] = s.simS[(t * 2 + 0) * PJ + r + 8] + acc2[2];
            s.attns[(t * 2 + 1) * PJ + r + 8] = s.simS[(t * 2 + 1) * PJ + r + 8] + acc2[3];
        }
    }
    __syncthreads();                                     // barrier 3

    // ---- batched exp + row sums: 32 rows x 8 lanes x 16 elems ----
    {
        int grp = tid >> 3;           // row = t*2 + head (0..31)
        int l8 = tid & 7;
        float4* ar = (float4*)(s.attns + grp * PJ) + l8 * 4;
        float ps = 0.f;
#pragma unroll
        for (int kk = 0; kk < 4; kk++) {
            float4 a = ar[kk];
            a.x = __expf(a.x); a.y = __expf(a.y);
            a.z = __expf(a.z); a.w = __expf(a.w);
            ar[kk] = a;
            ps += (a.x + a.y) + (a.z + a.w);
        }
        ps += __shfl_xor_sync(0xffffffffu, ps, 1);
        ps += __shfl_xor_sync(0xffffffffu, ps, 2);
        ps += __shfl_xor_sync(0xffffffffu, ps, 4);
        if (l8 == 0) s.sumS[grp] = ps;
    }
    __syncthreads();                                     // barrier 4

    // ---- attn @ V with deferred normalization ----
    {
        const int o = tid & 127, qh = tid >> 7, e = o >> 6;
        const ulonglong2* vrow = (const ulonglong2*)(g_v + (size_t)(bg * OFFD + o) * PJ);
        for (int t = qh * 8; t < qh * 8 + 8; t++) {
            float S = s.sumS[t * 2 + e];
            const ulonglong2* arow = (const ulonglong2*)(s.attns + (t * 2 + e) * PJ);
            unsigned long long accA = 0ull, accB = 0ull;
#pragma unroll
            for (int q = 0; q < 32; q++) {
                ulonglong2 av = arow[q];
                ulonglong2 vv = vrow[q];
                accA = ffma2(av.x, vv.x, accA);
                accB = ffma2(av.y, vv.y, accB);
            }
            float2 fa = unpack2(accA), fb = unpack2(accB);
            g_att[(size_t)(b * INNER + g * OFFD + o) * PQ + i0 + t] =
                (fa.x + fa.y + fb.x + fb.y) / S;
        }
    }
}

// ============================================================
// Kernel E: output projection (f32x2 packed inner product)
// ============================================================
__global__ void k_oproj(const float* __restrict__ wo, const float* __restrict__ bo,
                        float* __restrict__ out) {
    const int p0 = blockIdx.x * 64;
    const int o0 = blockIdx.y * 64;
    const int b = blockIdx.z;
    const int tid = threadIdx.x;
    const int tx = tid & 15, ty = tid >> 4;

    __shared__ __align__(16) float As[16 * 64];
    __shared__ __align__(16) float Bs[16 * 64];

    unsigned long long acc2[4][2];
#pragma unroll
    for (int a = 0; a < 4; a++) { acc2[a][0] = 0ull; acc2[a][1] = 0ull; }

    for (int k0 = 0; k0 < INNER; k0 += 16) {
        {
            int m = tid >> 2, kqq = (tid & 3) * 4;
            float4 wv = *(const float4*)(wo + (size_t)(o0 + m) * INNER + k0 + kqq);
            As[(kqq + 0) * 64 + m] = wv.x;
            As[(kqq + 1) * 64 + m] = wv.y;
            As[(kqq + 2) * 64 + m] = wv.z;
            As[(kqq + 3) * 64 + m] = wv.w;
            int k = tid >> 4, pq = (tid & 15) * 4;
            float4 bv = *(const float4*)(g_att + (size_t)(b * INNER + k0 + k) * PQ + p0 + pq);
            *(float4*)(Bs + k * 64 + pq) = bv;
        }
        __syncthreads();
#pragma unroll
        for (int k = 0; k < 16; k++) {
            float4 am = *(const float4*)(As + k * 64 + ty * 4);
            const unsigned long long* bn =
                (const unsigned long long*)(Bs + k * 64 + tx * 4);
            unsigned long long b0 = bn[0], b1 = bn[1];
            unsigned long long a0 = pack2(am.x, am.x);
            unsigned long long a1 = pack2(am.y, am.y);
            unsigned long long a2 = pack2(am.z, am.z);
            unsigned long long a3 = pack2(am.w, am.w);
            acc2[0][0] = ffma2(a0, b0, acc2[0][0]); acc2[0][1] = ffma2(a0, b1, acc2[0][1]);
            acc2[1][0] = ffma2(a1, b0, acc2[1][0]); acc2[1][1] = ffma2(a1, b1, acc2[1][1]);
            acc2[2][0] = ffma2(a2, b0, acc2[2][0]); acc2[2][1] = ffma2(a2, b1, acc2[2][1]);
            acc2[3][0] = ffma2(a3, b0, acc2[3][0]); acc2[3][1] = ffma2(a3, b1, acc2[3][1]);
        }
        __syncthreads();
    }
#pragma unroll
    for (int a = 0; a < 4; a++) {
        float bias = bo[o0 + ty * 4 + a];
        float2 c0 = unpack2(acc2[a][0]);
        float2 c1 = unpack2(acc2[a][1]);
        float* op = out + (size_t)(b * DIMC + o0 + ty * 4 + a) * PQ + p0 + tx * 4;
        op[0] = c0.x + bias;
        op[1] = c0.y + bias;
        op[2] = c1.x + bias;
        op[3] = c1.y + bias;
    }
}

// ============================================================
extern "C" void kernel_launch(void* const* d_in, const int* in_sizes, int n_in,
                              void* d_out, int out_size) {
    const float* x    = (const float*)d_in[0];
    const float* wq   = (const float*)d_in[1];
    const float* wk   = (const float*)d_in[2];
    const float* wv   = (const float*)d_in[3];
    const float* dww  = (const float*)d_in[4];
    const float* dwb  = (const float*)d_in[5];
    const float* pww  = (const float*)d_in[6];
    const float* cw0  = (const float*)d_in[7];
    const float* cb0  = (const float*)d_in[8];
    const float* cw1  = (const float*)d_in[9];
    const float* cb1  = (const float*)d_in[10];
    const float* cw2  = (const float*)d_in[11];
    const float* cb2  = (const float*)d_in[12];
    const float* wo   = (const float*)d_in[13];
    const float* bo   = (const float*)d_in[14];
    float* out = (float*)d_out;
    (void)cb2; // per-head constant bias cancels in softmax

    cudaFuncSetAttribute(k_attn, cudaFuncAttributeMaxDynamicSharedMemorySize,
                         (int)sizeof(SmemD));

    k_qproj<<<dim3(PQ / 16, NBG), 128>>>(x, wq);
    k_offsets<<<dim3(PJ, NBG), 128>>>(dww, dwb, pww);
    k_sample_kv<<<dim3(NBG, PJ / 16), 256>>>(x, wk, wv);
    k_attn<<<dim3(PQ / IT, NBG), 256, sizeof(SmemD)>>>(cw0, cb0, cw1, cb1, cw2, cb2);
    k_oproj<<<dim3(PQ / 64, DIMC / 64, BB), 256>>>(wo, bo, out);
}

// round 11
// speedup vs baseline: 1.4107x; 1.1557x over previous
#include <cuda_runtime.h>
#include <cuda_bf16.h>
#include <math.h>

// ---------------- problem constants ----------------
#define BB 2
#define DIMC 256
#define GG 4
#define CHG 64          // DIM/GROUPS
#define OFFD 128
#define NBG 8           // B*GROUPS
#define FF 4
#define HH 16
#define WW 16
#define PQ 1024         // F*H*W
#define PJ 128          // FD*HD*WD
#define CPB 64
#define INNER 512
#define IT 16           // queries per block in kernel D
#define KP 66           // padded K stride (halves) for w1 smem
#define WPAD 129        // padded float stride for staged weights (bank-conflict-free)

// ---------------- scratch ----------------
__device__ float g_q[NBG * OFFD * PQ];
__device__ float g_qT[NBG * PQ * OFFD];   // transposed copy: [bg][p][c]
__device__ float g_grid[NBG * PJ * 3];
__device__ float g_t[NBG * 3 * 16 * PJ];  // sign-log table [bg][d][v][j]
__device__ float g_k[NBG * OFFD * PJ];
__device__ float g_v[NBG * OFFD * PJ];
__device__ float g_att[BB * INNER * PQ];

// ---------------- helpers ----------------
__device__ __forceinline__ unsigned long long ffma2(unsigned long long a,
                                                    unsigned long long b,
                                                    unsigned long long c) {
    unsigned long long d;
    asm("fma.rn.f32x2 %0, %1, %2, %3;" : "=l"(d) : "l"(a), "l"(b), "l"(c));
    return d;
}
__device__ __forceinline__ unsigned long long pack2(float lo, float hi) {
    unsigned long long d;
    asm("mov.b64 %0, {%1, %2};" : "=l"(d) : "f"(lo), "f"(hi));
    return d;
}
__device__ __forceinline__ float2 unpack2(unsigned long long v) {
    float2 r;
    asm("mov.b64 {%0, %1}, %2;" : "=f"(r.x), "=f"(r.y) : "l"(v));
    return r;
}
__device__ __forceinline__ void mma16816(float* c, const unsigned* a, const unsigned* b) {
    asm volatile(
        "mma.sync.aligned.m16n8k16.row.col.f32.bf16.bf16.f32 "
        "{%0,%1,%2,%3}, {%4,%5,%6,%7}, {%8,%9}, {%0,%1,%2,%3};"
        : "+f"(c[0]), "+f"(c[1]), "+f"(c[2]), "+f"(c[3])
        : "r"(a[0]), "r"(a[1]), "r"(a[2]), "r"(a[3]), "r"(b[0]), "r"(b[1]));
}
__device__ __forceinline__ unsigned hfma2(unsigned a, unsigned b, unsigned c) {
    unsigned d;
    asm("fma.rn.bf16x2 %0, %1, %2, %3;" : "=r"(d) : "r"(a), "r"(b), "r"(c));
    return d;
}
__device__ __forceinline__ unsigned hadd2(unsigned a, unsigned b) {
    unsigned d;
    asm("add.rn.bf16x2 %0, %1, %2;" : "=r"(d) : "r"(a), "r"(b));
    return d;
}
__device__ __forceinline__ unsigned hmax2z(unsigned a) {
    unsigned d;
    asm("max.bf16x2 %0, %1, %2;" : "=r"(d) : "r"(a), "r"(0u));
    return d;
}
__device__ __forceinline__ unsigned packcvt(float lo, float hi) {
    unsigned d;
    asm("cvt.rn.bf16x2.f32 %0, %1, %2;" : "=r"(d) : "f"(hi), "f"(lo));
    return d;
}
__device__ __forceinline__ unsigned bcastbf(float x) {
    unsigned d;
    asm("cvt.rn.bf16x2.f32 %0, %1, %1;" : "=r"(d) : "f"(x));
    return d;
}

// ============================================================
// Kernel A: grouped 1x1 conv -> q (+ transposed copy g_qT)
// staged weights padded to WPAD (conflict-free STS)
// ============================================================
__global__ void k_qproj(const float* __restrict__ x, const float* __restrict__ wq) {
    const int bg = blockIdx.y;
    const int b = bg >> 2, g = bg & 3;
    const int p0 = blockIdx.x * 16;
    const int o = threadIdx.x;

    __shared__ __align__(16) float wqs[CHG * WPAD];   // [i][o] padded
    __shared__ __align__(16) float xs[CHG * 16];

    const float* wqg = wq + (size_t)g * OFFD * CHG;
    for (int e = o; e < OFFD * CHG; e += 128) {
        int oo = e >> 6, i = e & 63;
        wqs[i * WPAD + oo] = wqg[e];
    }
    for (int e = o; e < CHG * 16; e += 128) {
        int i = e >> 4, p = e & 15;
        xs[e] = x[(size_t)(b * DIMC + g * CHG + i) * PQ + p0 + p];
    }
    __syncthreads();

    unsigned long long acc2[8];
#pragma unroll
    for (int q = 0; q < 8; q++) acc2[q] = 0ull;

#pragma unroll 8
    for (int i = 0; i < CHG; i++) {
        float wv0 = wqs[i * WPAD + o];
        unsigned long long wv = pack2(wv0, wv0);
        const unsigned long long* xr = (const unsigned long long*)(xs + i * 16);
#pragma unroll
        for (int q = 0; q < 8; q++) acc2[q] = ffma2(wv, xr[q], acc2[q]);
    }
    float* qout = g_q + (size_t)(bg * OFFD + o) * PQ + p0;
    float* qtout = g_qT + ((size_t)bg * PQ + p0) * OFFD + o;
#pragma unroll
    for (int q = 0; q < 8; q++) {
        float2 f = unpack2(acc2[q]);
        qout[q * 2 + 0] = f.x;
        qout[q * 2 + 1] = f.y;
        qtout[(q * 2 + 0) * OFFD] = f.x;
        qtout[(q * 2 + 1) * OFFD] = f.y;
    }
}

// ============================================================
// Kernel B v2: 16 positions per block (grid 8x8, 256 thr),
// dws staged once (padded), 2 positions in flight
// ============================================================
__global__ __launch_bounds__(256)
void k_offsets(const float* __restrict__ dww, const float* __restrict__ dwb,
               const float* __restrict__ pww) {
    const int jt = blockIdx.x;      // 0..7 (16 positions each)
    const int bg = blockIdx.y;
    const int tid = threadIdx.x;
    const int half = tid >> 7;      // 0/1: which of the 2 concurrent positions
    const int c = tid & 127;
    const int lane = tid & 31;
    const int hw = (tid >> 5) & 3;  // warp index within half

    __shared__ __align__(16) float dws[64 * WPAD];    // [k][c] padded
    __shared__ __align__(16) float pws[3 * OFFD];
    __shared__ float dwbS[OFFD];
    __shared__ float acts[2][OFFD];
    __shared__ float sred[2][3];
    __shared__ float gcoord[2][3];

    for (int e = tid; e < 64 * OFFD; e += 256) {
        int cc = e >> 6, k = e & 63;
        dws[k * WPAD + cc] = dww[e];
    }
    for (int e = tid; e < 3 * OFFD; e += 256) pws[e] = pww[e];
    if (tid < OFFD) dwbS[tid] = dwb[tid];
    __syncthreads();

    const float* qT = g_qT + (size_t)bg * PQ * OFFD + c;

    for (int it = 0; it < 8; it++) {
        const int pos = jt * 16 + it * 2 + half;
        const int zo = pos >> 6;
        const int yo = (pos >> 3) & 7;
        const int xo = pos & 7;

        float acc = 0.f;
#pragma unroll
        for (int kz = 0; kz < 4; kz++) {
            int z = 2 * zo - 1 + kz;
            if (z < 0 || z >= FF) continue;
#pragma unroll
            for (int ky = 0; ky < 4; ky++) {
                int y = 2 * yo - 1 + ky;
                if (y < 0 || y >= HH) continue;
#pragma unroll
                for (int kx = 0; kx < 4; kx++) {
                    int xx = 2 * xo - 1 + kx;
                    if (xx < 0 || xx >= WW) continue;
                    int p = (z * HH + y) * WW + xx;
                    acc = fmaf(qT[(size_t)p * OFFD],
                               dws[((kz * 4 + ky) * 4 + kx) * WPAD + c], acc);
                }
            }
        }
        float v = acc + dwbS[c];
        acts[half][c] = 0.5f * v * (1.f + erff(v * 0.70710678118654752f));
        __syncthreads();

        if (hw < 3) {
            float s = 0.f;
#pragma unroll
            for (int q = 0; q < 4; q++) {
                int cc = lane + q * 32;
                s = fmaf(acts[half][cc], pws[hw * OFFD + cc], s);
            }
#pragma unroll
            for (int off = 16; off; off >>= 1)
                s += __shfl_xor_sync(0xffffffffu, s, off);
            if (lane == 0) sred[half][hw] = s;
        }
        __syncthreads();

        if (c < 3) {
            float off = tanhf(sred[half][c]) * 2.0f;
            int vo = (c == 0) ? zo : ((c == 1) ? yo : xo);
            float denom = (c == 0) ? 1.0f : 7.0f;
            float gcv = 2.0f * ((float)vo + off) / denom - 1.0f;
            gcoord[half][c] = gcv;
            g_grid[(size_t)(bg * PJ + pos) * 3 + c] = gcv;
        }
        __syncthreads();

        if (c < 36) {
            int d = (c < 4) ? 0 : ((c < 20) ? 1 : 2);
            int vq = (c < 4) ? c : ((c < 20) ? c - 4 : c - 20);
            float denom = (d == 0) ? 3.0f : 15.0f;
            float gq = 2.0f * (float)vq / denom - 1.0f;
            float p = gq - gcoord[half][d];
            g_t[(((size_t)bg * 3 + d) * 16 + vq) * PJ + pos] =
                copysignf(log1pf(fabsf(p)), p);
        }
    }
}

// ============================================================
// Kernel C: trilinear grid-sample + k/v projections (padded staging)
// ============================================================
__global__ __launch_bounds__(256)
void k_sample_kv(const float* __restrict__ x, const float* __restrict__ wk,
                 const float* __restrict__ wv) {
    const int bg = blockIdx.x;
    const int jt = blockIdx.y;
    const int b = bg >> 2, g = bg & 3;
    const int tid = threadIdx.x;

    __shared__ __align__(16) float wks[CHG * WPAD];
    __shared__ __align__(16) float wvs[CHG * WPAD];
    __shared__ __align__(16) float kvsS[16 * CHG];

    const float* wkg = wk + (size_t)g * OFFD * CHG;
    const float* wvg = wv + (size_t)g * OFFD * CHG;
    for (int e = tid; e < OFFD * CHG; e += 256) {
        int o = e >> 6, i = e & 63;
        wks[i * WPAD + o] = wkg[e];
        wvs[i * WPAD + o] = wvg[e];
    }

#pragma unroll
    for (int pass = 0; pass < 4; pass++) {
        int jl = pass * 4 + (tid >> 6);
        int ch = tid & 63;
        int j = jt * 16 + jl;
        const float* gp = g_grid + (size_t)(bg * PJ + j) * 3;
        float g0 = gp[0], g1 = gp[1], g2 = gp[2];
        float ix = ((g0 + 1.f) * (float)WW - 1.f) * 0.5f;
        float iy = ((g1 + 1.f) * (float)HH - 1.f) * 0.5f;
        float iz = ((g2 + 1.f) * (float)FF - 1.f) * 0.5f;
        float fx0 = floorf(ix), fy0 = floorf(iy), fz0 = floorf(iz);
        float tx = ix - fx0, ty = iy - fy0, tz = iz - fz0;
        int x0 = (int)fx0, y0 = (int)fy0, z0 = (int)fz0;

        const float* xp = x + (size_t)(b * DIMC + g * CHG + ch) * PQ;
        float acc = 0.f;
#pragma unroll
        for (int dz = 0; dz < 2; dz++)
#pragma unroll
            for (int dy = 0; dy < 2; dy++)
#pragma unroll
                for (int dx = 0; dx < 2; dx++) {
                    int xc = x0 + dx, yc = y0 + dy, zc = z0 + dz;
                    float wgt = (dx ? tx : 1.f - tx) * (dy ? ty : 1.f - ty) *
                                (dz ? tz : 1.f - tz);
                    bool valid = (xc >= 0) & (xc < WW) & (yc >= 0) & (yc < HH) &
                                 (zc >= 0) & (zc < FF);
                    int xi = min(max(xc, 0), WW - 1);
                    int yi = min(max(yc, 0), HH - 1);
                    int zi = min(max(zc, 0), FF - 1);
                    float val = xp[(zi * HH + yi) * WW + xi];
                    acc += valid ? val * wgt : 0.f;
                }
        kvsS[jl * CHG + ch] = acc;
    }
    __syncthreads();

    const int o = tid & 127;
    const int sel = tid >> 7;
    const float* ws = sel ? wvs : wks;
    float* gout = sel ? g_v : g_k;

    float acc[16];
#pragma unroll
    for (int jl = 0; jl < 16; jl++) acc[jl] = 0.f;
#pragma unroll 8
    for (int i = 0; i < CHG; i++) {
        float wv0 = ws[i * WPAD + o];
#pragma unroll
        for (int jl = 0; jl < 16; jl++)
            acc[jl] = fmaf(wv0, kvsS[jl * CHG + i], acc[jl]);
    }
    float* orow = gout + (size_t)(bg * OFFD + o) * PJ + jt * 16;
#pragma unroll
    for (int jl = 0; jl < 16; jl++) orow[jl] = acc[jl];
}

// ============================================================
// Kernel D v9: v8 + split acc2 chains (2-way ILP on the MMA critical path)
// ============================================================
struct __align__(16) SmemD {
    __nv_bfloat16 w1h[CPB * KP];
    float ts[IT * 3 * PJ];
    float qs[OFFD * IT];
    float attns[IT * 2 * PJ];
    float simS[IT * 2 * PJ];
    uint4 w0p[32];
    float w2s[CPB * 2];
    float b1s[CPB];
    float sumS[IT * 2];
};

__global__ __launch_bounds__(256, 2)
void k_attn(const float* __restrict__ cw0, const float* __restrict__ cb0,
            const float* __restrict__ cw1, const float* __restrict__ cb1,
            const float* __restrict__ cw2, const float* __restrict__ cb2) {
    extern __shared__ SmemD smD[];
    SmemD& s = smD[0];

    const int bg = blockIdx.y;
    const int b = bg >> 2, g = bg & 3;
    const int i0 = blockIdx.x * IT;
    const int tid = threadIdx.x;
    const int lane = tid & 31, w = tid >> 5;

    // ---- stage ----
    for (int e = tid; e < CPB * CPB; e += 256) {
        int k = e >> 6, n = e & 63;
        s.w1h[n * KP + k] = __float2bfloat16_rn(cw1[e]);
    }
    if (tid < 32) {
        int c = tid * 2;
        uint4 wp;
        wp.x = packcvt(cw0[c], cw0[c + 1]);
        wp.y = packcvt(cw0[64 + c], cw0[64 + c + 1]);
        wp.z = packcvt(cw0[128 + c], cw0[128 + c + 1]);
        wp.w = packcvt(cb0[c], cb0[c + 1]);
        s.w0p[tid] = wp;
    }
    if (tid >= 64 && tid < 192) s.w2s[tid - 64] = cw2[tid - 64];
    if (tid >= 192) s.b1s[tid - 192] = cb1[tid - 192];
    {
        int o = tid >> 1, half = (tid & 1) * 8;
        const float* qp = g_q + (size_t)(bg * OFFD + o) * PQ + i0 + half;
        float4 qv0 = *(const float4*)qp;
        float4 qv1 = *(const float4*)(qp + 4);
        s.qs[o * IT + half + 0] = qv0.x * 0.125f;
        s.qs[o * IT + half + 1] = qv0.y * 0.125f;
        s.qs[o * IT + half + 2] = qv0.z * 0.125f;
        s.qs[o * IT + half + 3] = qv0.w * 0.125f;
        s.qs[o * IT + half + 4] = qv1.x * 0.125f;
        s.qs[o * IT + half + 5] = qv1.y * 0.125f;
        s.qs[o * IT + half + 6] = qv1.z * 0.125f;
        s.qs[o * IT + half + 7] = qv1.w * 0.125f;
    }
    for (int e = tid; e < IT * 3 * PJ; e += 256) {
        int q = e / 384, rem = e - q * 384;
        int d = rem >> 7, j = rem & 127;
        int i = i0 + q;
        int vq = (d == 0) ? (i >> 8) : ((d == 1) ? ((i >> 4) & 15) : (i & 15));
        s.ts[e] = g_t[(((size_t)bg * 3 + d) * 16 + vq) * PJ + j];
    }
    __syncthreads();                                     // barrier 1

    const int r = w * 16 + (lane >> 2);
    const int q2 = lane & 3;
    const int kq = q2 * 2;
    const int nl = lane >> 2;

    // ---- hoist w1 B-fragments into registers ----
    unsigned bfr[8][4][2];
#pragma unroll
    for (int nf = 0; nf < 8; nf++) {
        int nrow = nf * 8 + nl;
#pragma unroll
        for (int kt = 0; kt < 4; kt++) {
            bfr[nf][kt][0] = *(const unsigned*)&s.w1h[nrow * KP + kt * 16 + kq];
            bfr[nf][kt][1] = *(const unsigned*)&s.w1h[nrow * KP + kt * 16 + kq + 8];
        }
    }
    unsigned bw2[4][2], b1p[4][2];
#pragma unroll
    for (int kt2 = 0; kt2 < 4; kt2++) {
        int k0 = kt2 * 16 + kq;
        bw2[kt2][0] = (nl < 2) ? packcvt(s.w2s[k0 * 2 + nl], s.w2s[(k0 + 1) * 2 + nl]) : 0u;
        bw2[kt2][1] = (nl < 2) ? packcvt(s.w2s[(k0 + 8) * 2 + nl], s.w2s[(k0 + 9) * 2 + nl]) : 0u;
        b1p[kt2][0] = packcvt(s.b1s[k0], s.b1s[k0 + 1]);
        b1p[kt2][1] = packcvt(s.b1s[k0 + 8], s.b1s[k0 + 9]);
    }

    // ---- sim -> smem (j-owner layout), f32x2, 16 queries ----
    {
        const int jj = tid & 127, eh = tid >> 7;
        unsigned long long sim2[8];
#pragma unroll
        for (int h = 0; h < 8; h++) sim2[h] = 0ull;
        const float* kb = g_k + (size_t)bg * OFFD * PJ + (size_t)eh * 64 * PJ + jj;
#pragma unroll 4
        for (int o = 0; o < 64; o++) {
            float kv = kb[o * PJ];
            unsigned long long kvp = pack2(kv, kv);
            const unsigned long long* qp =
                (const unsigned long long*)(s.qs + (eh * 64 + o) * IT);
#pragma unroll
            for (int h = 0; h < 8; h++) sim2[h] = ffma2(qp[h], kvp, sim2[h]);
        }
#pragma unroll
        for (int h = 0; h < 8; h++) {
            float2 f = unpack2(sim2[h]);
            s.simS[((2 * h + 0) * 2 + eh) * PJ + jj] = f.x;
            s.simS[((2 * h + 1) * 2 + eh) * PJ + jj] = f.y;
        }
    }
    __syncthreads();                                     // barrier 2

    // ---- per-query loop: logits only, 2 independent MMA chains ----
    for (int t = 0; t < IT; t++) {
        const float* tq = s.ts + t * 3 * PJ;
        unsigned tp0[3], tp1[3];
#pragma unroll
        for (int d = 0; d < 3; d++) {
            tp0[d] = bcastbf(tq[d * PJ + r]);
            tp1[d] = bcastbf(tq[d * PJ + r + 8]);
        }

        unsigned ah[16];
#pragma unroll
        for (int kt = 0; kt < 4; kt++) {
#pragma unroll
            for (int cp = 0; cp < 2; cp++) {
                uint4 W = s.w0p[kt * 8 + q2 + cp * 4];
                ah[kt * 4 + cp * 2 + 0] =
                    hmax2z(hfma2(tp0[0], W.x, hfma2(tp0[1], W.y, hfma2(tp0[2], W.z, W.w))));
                ah[kt * 4 + cp * 2 + 1] =
                    hmax2z(hfma2(tp1[0], W.x, hfma2(tp1[1], W.y, hfma2(tp1[2], W.z, W.w))));
            }
        }

        float acc2a[4] = {0.f, 0.f, 0.f, 0.f};
        float acc2b[4] = {0.f, 0.f, 0.f, 0.f};
#pragma unroll
        for (int kt2 = 0; kt2 < 4; kt2++) {
            float accA[4] = {0.f, 0.f, 0.f, 0.f};
            float accB[4] = {0.f, 0.f, 0.f, 0.f};
#pragma unroll
            for (int kt = 0; kt < 4; kt++) {
                mma16816(accA, &ah[kt * 4], bfr[2 * kt2][kt]);
                mma16816(accB, &ah[kt * 4], bfr[2 * kt2 + 1][kt]);
            }
            unsigned a2[4];
            a2[0] = hmax2z(hadd2(packcvt(accA[0], accA[1]), b1p[kt2][0]));
            a2[1] = hmax2z(hadd2(packcvt(accA[2], accA[3]), b1p[kt2][0]));
            a2[2] = hmax2z(hadd2(packcvt(accB[0], accB[1]), b1p[kt2][1]));
            a2[3] = hmax2z(hadd2(packcvt(accB[2], accB[3]), b1p[kt2][1]));
            mma16816((kt2 < 2) ? acc2a : acc2b, a2, bw2[kt2]);
        }

        if (q2 == 0) {
            s.attns[(t * 2 + 0) * PJ + r]     = s.simS[(t * 2 + 0) * PJ + r] + acc2a[0] + acc2b[0];
            s.attns[(t * 2 + 1) * PJ + r]     = s.simS[(t * 2 + 1) * PJ + r] + acc2a[1] + acc2b[1];
            s.attns[(t * 2 + 0) * PJ + r + 8] = s.simS[(t * 2 + 0) * PJ + r + 8] + acc2a[2] + acc2b[2];
            s.attns[(t * 2 + 1) * PJ + r + 8] = s.simS[(t * 2 + 1) * PJ + r + 8] + acc2a[3] + acc2b[3];
        }
    }
    __syncthreads();                                     // barrier 3

    // ---- batched exp + row sums ----
    {
        int grp = tid >> 3;
        int l8 = tid & 7;
        float4* ar = (float4*)(s.attns + grp * PJ) + l8 * 4;
        float ps = 0.f;
#pragma unroll
        for (int kk = 0; kk < 4; kk++) {
            float4 a = ar[kk];
            a.x = __expf(a.x); a.y = __expf(a.y);
            a.z = __expf(a.z); a.w = __expf(a.w);
            ar[kk] = a;
            ps += (a.x + a.y) + (a.z + a.w);
        }
        ps += __shfl_xor_sync(0xffffffffu, ps, 1);
        ps += __shfl_xor_sync(0xffffffffu, ps, 2);
        ps += __shfl_xor_sync(0xffffffffu, ps, 4);
        if (l8 == 0) s.sumS[grp] = ps;
    }
    __syncthreads();                                     // barrier 4

    // ---- attn @ V with deferred normalization ----
    {
        const int o = tid & 127, qh = tid >> 7, e = o >> 6;
        const ulonglong2* vrow = (const ulonglong2*)(g_v + (size_t)(bg * OFFD + o) * PJ);
        for (int t = qh * 8; t < qh * 8 + 8; t++) {
            float S = s.sumS[t * 2 + e];
            const ulonglong2* arow = (const ulonglong2*)(s.attns + (t * 2 + e) * PJ);
            unsigned long long accA = 0ull, accB = 0ull;
#pragma unroll
            for (int q = 0; q < 32; q++) {
                ulonglong2 av = arow[q];
                ulonglong2 vv = vrow[q];
                accA = ffma2(av.x, vv.x, accA);
                accB = ffma2(av.y, vv.y, accB);
            }
            float2 fa = unpack2(accA), fb = unpack2(accB);
            g_att[(size_t)(b * INNER + g * OFFD + o) * PQ + i0 + t] =
                (fa.x + fa.y + fb.x + fb.y) / S;
        }
    }
}

// ============================================================
// Kernel E: output projection (As padded to 65)
// ============================================================
__global__ void k_oproj(const float* __restrict__ wo, const float* __restrict__ bo,
                        float* __restrict__ out) {
    const int p0 = blockIdx.x * 64;
    const int o0 = blockIdx.y * 64;
    const int b = blockIdx.z;
    const int tid = threadIdx.x;
    const int tx = tid & 15, ty = tid >> 4;

    __shared__ __align__(16) float As[16 * 65];
    __shared__ __align__(16) float Bs[16 * 64];

    unsigned long long acc2[4][2];
#pragma unroll
    for (int a = 0; a < 4; a++) { acc2[a][0] = 0ull; acc2[a][1] = 0ull; }

    for (int k0 = 0; k0 < INNER; k0 += 16) {
        {
            int m = tid >> 2, kqq = (tid & 3) * 4;
            float4 wv = *(const float4*)(wo + (size_t)(o0 + m) * INNER + k0 + kqq);
            As[(kqq + 0) * 65 + m] = wv.x;
            As[(kqq + 1) * 65 + m] = wv.y;
            As[(kqq + 2) * 65 + m] = wv.z;
            As[(kqq + 3) * 65 + m] = wv.w;
            int k = tid >> 4, pq = (tid & 15) * 4;
            float4 bv = *(const float4*)(g_att + (size_t)(b * INNER + k0 + k) * PQ + p0 + pq);
            *(float4*)(Bs + k * 64 + pq) = bv;
        }
        __syncthreads();
#pragma unroll
        for (int k = 0; k < 16; k++) {
            const float* am = As + k * 65 + ty * 4;
            float a0f = am[0], a1f = am[1], a2f = am[2], a3f = am[3];
            const unsigned long long* bn =
                (const unsigned long long*)(Bs + k * 64 + tx * 4);
            unsigned long long b0 = bn[0], b1 = bn[1];
            unsigned long long a0 = pack2(a0f, a0f);
            unsigned long long a1 = pack2(a1f, a1f);
            unsigned long long a2 = pack2(a2f, a2f);
            unsigned long long a3 = pack2(a3f, a3f);
            acc2[0][0] = ffma2(a0, b0, acc2[0][0]); acc2[0][1] = ffma2(a0, b1, acc2[0][1]);
            acc2[1][0] = ffma2(a1, b0, acc2[1][0]); acc2[1][1] = ffma2(a1, b1, acc2[1][1]);
            acc2[2][0] = ffma2(a2, b0, acc2[2][0]); acc2[2][1] = ffma2(a2, b1, acc2[2][1]);
            acc2[3][0] = ffma2(a3, b0, acc2[3][0]); acc2[3][1] = ffma2(a3, b1, acc2[3][1]);
        }
        __syncthreads();
    }
#pragma unroll
    for (int a = 0; a < 4; a++) {
        float bias = bo[o0 + ty * 4 + a];
        float2 c0 = unpack2(acc2[a][0]);
        float2 c1 = unpack2(acc2[a][1]);
        float* op = out + (size_t)(b * DIMC + o0 + ty * 4 + a) * PQ + p0 + tx * 4;
        op[0] = c0.x + bias;
        op[1] = c0.y + bias;
        op[2] = c1.x + bias;
        op[3] = c1.y + bias;
    }
}

// ============================================================
extern "C" void kernel_launch(void* const* d_in, const int* in_sizes, int n_in,
                              void* d_out, int out_size) {
    const float* x    = (const float*)d_in[0];
    const float* wq   = (const float*)d_in[1];
    const float* wk   = (const float*)d_in[2];
    const float* wv   = (const float*)d_in[3];
    const float* dww  = (const float*)d_in[4];
    const float* dwb  = (const float*)d_in[5];
    const float* pww  = (const float*)d_in[6];
    const float* cw0  = (const float*)d_in[7];
    const float* cb0  = (const float*)d_in[8];
    const float* cw1  = (const float*)d_in[9];
    const float* cb1  = (const float*)d_in[10];
    const float* cw2  = (const float*)d_in[11];
    const float* cb2  = (const float*)d_in[12];
    const float* wo   = (const float*)d_in[13];
    const float* bo   = (const float*)d_in[14];
    float* out = (float*)d_out;
    (void)cb2; // per-head constant bias cancels in softmax

    cudaFuncSetAttribute(k_attn, cudaFuncAttributeMaxDynamicSharedMemorySize,
                         (int)sizeof(SmemD));

    k_qproj<<<dim3(PQ / 16, NBG), 128>>>(x, wq);
    k_offsets<<<dim3(8, NBG), 256>>>(dww, dwb, pww);
    k_sample_kv<<<dim3(NBG, PJ / 16), 256>>>(x, wk, wv);
    k_attn<<<dim3(PQ / IT, NBG), 256, sizeof(SmemD)>>>(cw0, cb0, cw1, cb1, cw2, cb2);
    k_oproj<<<dim3(PQ / 64, DIMC / 64, BB), 256>>>(wo, bo, out);
}

// round 12
// speedup vs baseline: 1.6217x; 1.1495x over previous
#include <cuda_runtime.h>
#include <cuda_bf16.h>
#include <math.h>

// ---------------- problem constants ----------------
#define BB 2
#define DIMC 256
#define GG 4
#define CHG 64          // DIM/GROUPS
#define OFFD 128
#define NBG 8           // B*GROUPS
#define FF 4
#define HH 16
#define WW 16
#define PQ 1024         // F*H*W
#define PJ 128          // FD*HD*WD
#define CPB 64
#define INNER 512
#define IT 16           // queries per block in kernel D
#define KP 66           // padded K stride (halves) for w1 smem
#define KSP 72          // padded stride for kh/kl/qb bf16 tiles
#define SIMP 130        // padded float stride for simS
#define WPAD 129        // padded float stride for staged weights

// ---------------- scratch ----------------
__device__ float g_qT[NBG * PQ * OFFD];              // [bg][p][c]
__device__ float g_grid[NBG * PJ * 3];
__device__ __nv_bfloat16 g_t_bf[NBG * 3 * 16 * PJ];  // sign-log table (bf16)
__device__ __nv_bfloat16 g_khT[NBG * PJ * OFFD];     // k hi, [bg][j][o]
__device__ __nv_bfloat16 g_klT[NBG * PJ * OFFD];     // k lo
__device__ float g_v[NBG * OFFD * PJ];
__device__ float g_att[BB * INNER * PQ];

// ---------------- helpers ----------------
__device__ __forceinline__ unsigned long long ffma2(unsigned long long a,
                                                    unsigned long long b,
                                                    unsigned long long c) {
    unsigned long long d;
    asm("fma.rn.f32x2 %0, %1, %2, %3;" : "=l"(d) : "l"(a), "l"(b), "l"(c));
    return d;
}
__device__ __forceinline__ unsigned long long pack2(float lo, float hi) {
    unsigned long long d;
    asm("mov.b64 %0, {%1, %2};" : "=l"(d) : "f"(lo), "f"(hi));
    return d;
}
__device__ __forceinline__ float2 unpack2(unsigned long long v) {
    float2 r;
    asm("mov.b64 {%0, %1}, %2;" : "=f"(r.x), "=f"(r.y) : "l"(v));
    return r;
}
__device__ __forceinline__ void mma16816(float* c, const unsigned* a, const unsigned* b) {
    asm volatile(
        "mma.sync.aligned.m16n8k16.row.col.f32.bf16.bf16.f32 "
        "{%0,%1,%2,%3}, {%4,%5,%6,%7}, {%8,%9}, {%0,%1,%2,%3};"
        : "+f"(c[0]), "+f"(c[1]), "+f"(c[2]), "+f"(c[3])
        : "r"(a[0]), "r"(a[1]), "r"(a[2]), "r"(a[3]), "r"(b[0]), "r"(b[1]));
}
__device__ __forceinline__ unsigned hfma2(unsigned a, unsigned b, unsigned c) {
    unsigned d;
    asm("fma.rn.bf16x2 %0, %1, %2, %3;" : "=r"(d) : "r"(a), "r"(b), "r"(c));
    return d;
}
__device__ __forceinline__ unsigned hadd2(unsigned a, unsigned b) {
    unsigned d;
    asm("add.rn.bf16x2 %0, %1, %2;" : "=r"(d) : "r"(a), "r"(b));
    return d;
}
__device__ __forceinline__ unsigned hmax2z(unsigned a) {
    unsigned d;
    asm("max.bf16x2 %0, %1, %2;" : "=r"(d) : "r"(a), "r"(0u));
    return d;
}
__device__ __forceinline__ unsigned packcvt(float lo, float hi) {
    unsigned d;
    asm("cvt.rn.bf16x2.f32 %0, %1, %2;" : "=r"(d) : "f"(hi), "f"(lo));
    return d;
}

// ============================================================
// Kernel A: grouped 1x1 conv -> q (transposed layout only)
// ============================================================
__global__ void k_qproj(const float* __restrict__ x, const float* __restrict__ wq) {
    const int bg = blockIdx.y;
    const int b = bg >> 2, g = bg & 3;
    const int p0 = blockIdx.x * 16;
    const int o = threadIdx.x;

    __shared__ __align__(16) float wqs[CHG * WPAD];   // [i][o] padded
    __shared__ __align__(16) float xs[CHG * 16];

    const float* wqg = wq + (size_t)g * OFFD * CHG;
    for (int e = o; e < OFFD * CHG; e += 128) {
        int oo = e >> 6, i = e & 63;
        wqs[i * WPAD + oo] = wqg[e];
    }
    for (int e = o; e < CHG * 16; e += 128) {
        int i = e >> 4, p = e & 15;
        xs[e] = x[(size_t)(b * DIMC + g * CHG + i) * PQ + p0 + p];
    }
    __syncthreads();

    unsigned long long acc2[8];
#pragma unroll
    for (int q = 0; q < 8; q++) acc2[q] = 0ull;

#pragma unroll 8
    for (int i = 0; i < CHG; i++) {
        float wv0 = wqs[i * WPAD + o];
        unsigned long long wv = pack2(wv0, wv0);
        const unsigned long long* xr = (const unsigned long long*)(xs + i * 16);
#pragma unroll
        for (int q = 0; q < 8; q++) acc2[q] = ffma2(wv, xr[q], acc2[q]);
    }
    float* qtout = g_qT + ((size_t)bg * PQ + p0) * OFFD + o;
#pragma unroll
    for (int q = 0; q < 8; q++) {
        float2 f = unpack2(acc2[q]);
        qtout[(q * 2 + 0) * OFFD] = f.x;
        qtout[(q * 2 + 1) * OFFD] = f.y;
    }
}

// ============================================================
// Kernel B: offsets -> grid coords + bf16 sign-log table
// ============================================================
__global__ __launch_bounds__(256)
void k_offsets(const float* __restrict__ dww, const float* __restrict__ dwb,
               const float* __restrict__ pww) {
    const int jt = blockIdx.x;
    const int bg = blockIdx.y;
    const int tid = threadIdx.x;
    const int half = tid >> 7;
    const int c = tid & 127;
    const int lane = tid & 31;
    const int hw = (tid >> 5) & 3;

    __shared__ __align__(16) float dws[64 * WPAD];
    __shared__ __align__(16) float pws[3 * OFFD];
    __shared__ float dwbS[OFFD];
    __shared__ float acts[2][OFFD];
    __shared__ float sred[2][3];
    __shared__ float gcoord[2][3];

    for (int e = tid; e < 64 * OFFD; e += 256) {
        int cc = e >> 6, k = e & 63;
        dws[k * WPAD + cc] = dww[e];
    }
    for (int e = tid; e < 3 * OFFD; e += 256) pws[e] = pww[e];
    if (tid < OFFD) dwbS[tid] = dwb[tid];
    __syncthreads();

    const float* qT = g_qT + (size_t)bg * PQ * OFFD + c;

    for (int it = 0; it < 8; it++) {
        const int pos = jt * 16 + it * 2 + half;
        const int zo = pos >> 6;
        const int yo = (pos >> 3) & 7;
        const int xo = pos & 7;

        float acc = 0.f;
#pragma unroll
        for (int kz = 0; kz < 4; kz++) {
            int z = 2 * zo - 1 + kz;
            if (z < 0 || z >= FF) continue;
#pragma unroll
            for (int ky = 0; ky < 4; ky++) {
                int y = 2 * yo - 1 + ky;
                if (y < 0 || y >= HH) continue;
#pragma unroll
                for (int kx = 0; kx < 4; kx++) {
                    int xx = 2 * xo - 1 + kx;
                    if (xx < 0 || xx >= WW) continue;
                    int p = (z * HH + y) * WW + xx;
                    acc = fmaf(qT[(size_t)p * OFFD],
                               dws[((kz * 4 + ky) * 4 + kx) * WPAD + c], acc);
                }
            }
        }
        float v = acc + dwbS[c];
        acts[half][c] = 0.5f * v * (1.f + erff(v * 0.70710678118654752f));
        __syncthreads();

        if (hw < 3) {
            float s = 0.f;
#pragma unroll
            for (int q = 0; q < 4; q++) {
                int cc = lane + q * 32;
                s = fmaf(acts[half][cc], pws[hw * OFFD + cc], s);
            }
#pragma unroll
            for (int off = 16; off; off >>= 1)
                s += __shfl_xor_sync(0xffffffffu, s, off);
            if (lane == 0) sred[half][hw] = s;
        }
        __syncthreads();

        if (c < 3) {
            float off = tanhf(sred[half][c]) * 2.0f;
            int vo = (c == 0) ? zo : ((c == 1) ? yo : xo);
            float denom = (c == 0) ? 1.0f : 7.0f;
            float gcv = 2.0f * ((float)vo + off) / denom - 1.0f;
            gcoord[half][c] = gcv;
            g_grid[(size_t)(bg * PJ + pos) * 3 + c] = gcv;
        }
        __syncthreads();

        if (c < 36) {
            int d = (c < 4) ? 0 : ((c < 20) ? 1 : 2);
            int vq = (c < 4) ? c : ((c < 20) ? c - 4 : c - 20);
            float denom = (d == 0) ? 3.0f : 15.0f;
            float gq = 2.0f * (float)vq / denom - 1.0f;
            float p = gq - gcoord[half][d];
            g_t_bf[(((size_t)bg * 3 + d) * 16 + vq) * PJ + pos] =
                __float2bfloat16_rn(copysignf(log1pf(fabsf(p)), p));
        }
    }
}

// ============================================================
// Kernel C: trilinear grid-sample + k/v projections
// k written as hi/lo bf16 transposed [bg][j][o] (for sim MMA)
// ============================================================
__global__ __launch_bounds__(256)
void k_sample_kv(const float* __restrict__ x, const float* __restrict__ wk,
                 const float* __restrict__ wv) {
    const int bg = blockIdx.x;
    const int jt = blockIdx.y;
    const int b = bg >> 2, g = bg & 3;
    const int tid = threadIdx.x;

    __shared__ __align__(16) float wks[CHG * WPAD];
    __shared__ __align__(16) float wvs[CHG * WPAD];
    __shared__ __align__(16) float kvsS[16 * CHG];

    const float* wkg = wk + (size_t)g * OFFD * CHG;
    const float* wvg = wv + (size_t)g * OFFD * CHG;
    for (int e = tid; e < OFFD * CHG; e += 256) {
        int o = e >> 6, i = e & 63;
        wks[i * WPAD + o] = wkg[e];
        wvs[i * WPAD + o] = wvg[e];
    }

#pragma unroll
    for (int pass = 0; pass < 4; pass++) {
        int jl = pass * 4 + (tid >> 6);
        int ch = tid & 63;
        int j = jt * 16 + jl;
        const float* gp = g_grid + (size_t)(bg * PJ + j) * 3;
        float g0 = gp[0], g1 = gp[1], g2 = gp[2];
        float ix = ((g0 + 1.f) * (float)WW - 1.f) * 0.5f;
        float iy = ((g1 + 1.f) * (float)HH - 1.f) * 0.5f;
        float iz = ((g2 + 1.f) * (float)FF - 1.f) * 0.5f;
        float fx0 = floorf(ix), fy0 = floorf(iy), fz0 = floorf(iz);
        float tx = ix - fx0, ty = iy - fy0, tz = iz - fz0;
        int x0 = (int)fx0, y0 = (int)fy0, z0 = (int)fz0;

        const float* xp = x + (size_t)(b * DIMC + g * CHG + ch) * PQ;
        float acc = 0.f;
#pragma unroll
        for (int dz = 0; dz < 2; dz++)
#pragma unroll
            for (int dy = 0; dy < 2; dy++)
#pragma unroll
                for (int dx = 0; dx < 2; dx++) {
                    int xc = x0 + dx, yc = y0 + dy, zc = z0 + dz;
                    float wgt = (dx ? tx : 1.f - tx) * (dy ? ty : 1.f - ty) *
                                (dz ? tz : 1.f - tz);
                    bool valid = (xc >= 0) & (xc < WW) & (yc >= 0) & (yc < HH) &
                                 (zc >= 0) & (zc < FF);
                    int xi = min(max(xc, 0), WW - 1);
                    int yi = min(max(yc, 0), HH - 1);
                    int zi = min(max(zc, 0), FF - 1);
                    float val = xp[(zi * HH + yi) * WW + xi];
                    acc += valid ? val * wgt : 0.f;
                }
        kvsS[jl * CHG + ch] = acc;
    }
    __syncthreads();

    const int o = tid & 127;
    const int sel = tid >> 7;
    const float* ws = sel ? wvs : wks;

    float acc[16];
#pragma unroll
    for (int jl = 0; jl < 16; jl++) acc[jl] = 0.f;
#pragma unroll 8
    for (int i = 0; i < CHG; i++) {
        float wv0 = ws[i * WPAD + o];
#pragma unroll
        for (int jl = 0; jl < 16; jl++)
            acc[jl] = fmaf(wv0, kvsS[jl * CHG + i], acc[jl]);
    }
    if (sel) {
        float* orow = g_v + (size_t)(bg * OFFD + o) * PJ + jt * 16;
#pragma unroll
        for (int jl = 0; jl < 16; jl++) orow[jl] = acc[jl];
    } else {
#pragma unroll
        for (int jl = 0; jl < 16; jl++) {
            float ak = acc[jl];
            __nv_bfloat16 hi = __float2bfloat16_rn(ak);
            __nv_bfloat16 lo = __float2bfloat16_rn(ak - __bfloat162float(hi));
            size_t idx = ((size_t)bg * PJ + jt * 16 + jl) * OFFD + o;
            g_khT[idx] = hi;
            g_klT[idx] = lo;
        }
    }
}

// ============================================================
// Kernel D v10: sim via 3-term bf16 MMA; ts as bf16;
// attn@V loop-swapped (V rows hoisted). Query loop = proven v8 core.
// ============================================================
struct __align__(16) SmemD {
    __nv_bfloat16 w1h[CPB * KP];          // 8448 B
    __nv_bfloat16 kh[PJ * KSP];           // 18432 B (per-head staging)
    __nv_bfloat16 kl[PJ * KSP];           // 18432 B
    __nv_bfloat16 qbh[16 * KSP];          // 2304 B
    __nv_bfloat16 qbl[16 * KSP];          // 2304 B
    __nv_bfloat16 ts_bf[IT * 3 * PJ];     // 12288 B
    float attns[IT * 2 * PJ];             // 16384 B
    float simS[IT * 2 * SIMP];            // 16640 B
    uint4 w0p[32];
    float w2s[CPB * 2];
    float b1s[CPB];
    float sumS[IT * 2];
};

__global__ __launch_bounds__(256, 2)
void k_attn(const float* __restrict__ cw0, const float* __restrict__ cb0,
            const float* __restrict__ cw1, const float* __restrict__ cb1,
            const float* __restrict__ cw2, const float* __restrict__ cb2) {
    extern __shared__ SmemD smD[];
    SmemD& s = smD[0];

    const int bg = blockIdx.y;
    const int b = bg >> 2, g = bg & 3;
    const int i0 = blockIdx.x * IT;
    const int tid = threadIdx.x;
    const int lane = tid & 31, w = tid >> 5;

    // ---- stage block-invariant tables ----
    for (int e = tid; e < CPB * CPB; e += 256) {
        int k = e >> 6, n = e & 63;
        s.w1h[n * KP + k] = __float2bfloat16_rn(cw1[e]);
    }
    if (tid < 32) {
        int c = tid * 2;
        uint4 wp;
        wp.x = packcvt(cw0[c], cw0[c + 1]);
        wp.y = packcvt(cw0[64 + c], cw0[64 + c + 1]);
        wp.z = packcvt(cw0[128 + c], cw0[128 + c + 1]);
        wp.w = packcvt(cb0[c], cb0[c + 1]);
        s.w0p[tid] = wp;
    }
    if (tid >= 64 && tid < 192) s.w2s[tid - 64] = cw2[tid - 64];
    if (tid >= 192) s.b1s[tid - 192] = cb1[tid - 192];
    // ts_bf: 48 rows (q*3+d) of 128 bf16, uint4 copies from g_t_bf
    for (int e = tid; e < 768; e += 256) {
        int row = e >> 4, seg = e & 15;
        int q = row / 3, d = row - q * 3;
        int i = i0 + q;
        int vq = (d == 0) ? (i >> 8) : ((d == 1) ? ((i >> 4) & 15) : (i & 15));
        *(uint4*)&s.ts_bf[row * PJ + seg * 8] =
            *(const uint4*)&g_t_bf[(((size_t)bg * 3 + d) * 16 + vq) * PJ + seg * 8];
    }
    __syncthreads();                                     // barrier 1

    const int r = w * 16 + (lane >> 2);
    const int q2 = lane & 3;
    const int kq = q2 * 2;
    const int nl = lane >> 2;

    // ---- hoist w1 B-fragments into registers ----
    unsigned bfr[8][4][2];
#pragma unroll
    for (int nf = 0; nf < 8; nf++) {
        int nrow = nf * 8 + nl;
#pragma unroll
        for (int kt = 0; kt < 4; kt++) {
            bfr[nf][kt][0] = *(const unsigned*)&s.w1h[nrow * KP + kt * 16 + kq];
            bfr[nf][kt][1] = *(const unsigned*)&s.w1h[nrow * KP + kt * 16 + kq + 8];
        }
    }
    unsigned bw2[4][2], b1p[4][2];
#pragma unroll
    for (int kt2 = 0; kt2 < 4; kt2++) {
        int k0 = kt2 * 16 + kq;
        bw2[kt2][0] = (nl < 2) ? packcvt(s.w2s[k0 * 2 + nl], s.w2s[(k0 + 1) * 2 + nl]) : 0u;
        bw2[kt2][1] = (nl < 2) ? packcvt(s.w2s[(k0 + 8) * 2 + nl], s.w2s[(k0 + 9) * 2 + nl]) : 0u;
        b1p[kt2][0] = packcvt(s.b1s[k0], s.b1s[k0 + 1]);
        b1p[kt2][1] = packcvt(s.b1s[k0 + 8], s.b1s[k0 + 9]);
    }

    // ---- sim via MMA: per head, stage K hi/lo + Q hi/lo then 3-term MMAs ----
    for (int h = 0; h < 2; h++) {
        // K tiles: 128 rows x 64 bf16, uint4 copies
        for (int e = tid; e < 1024; e += 256) {
            int row = e >> 3, seg = e & 7;
            size_t src = ((size_t)bg * PJ + row) * OFFD + h * 64 + seg * 8;
            *(uint4*)&s.kh[row * KSP + seg * 8] = *(const uint4*)&g_khT[src];
            *(uint4*)&s.kl[row * KSP + seg * 8] = *(const uint4*)&g_klT[src];
        }
        // Q tile: 16 t x 64 o, scaled + hi/lo split
        {
            int base = tid * 4;
            int t = base >> 6, o = base & 63;
            float4 qv = *(const float4*)&g_qT[((size_t)bg * PQ + i0 + t) * OFFD + h * 64 + o];
            float q0 = qv.x * 0.125f, q1 = qv.y * 0.125f,
                  q2f = qv.z * 0.125f, q3 = qv.w * 0.125f;
            __nv_bfloat16 h0 = __float2bfloat16_rn(q0);
            __nv_bfloat16 h1 = __float2bfloat16_rn(q1);
            __nv_bfloat16 h2 = __float2bfloat16_rn(q2f);
            __nv_bfloat16 h3 = __float2bfloat16_rn(q3);
            s.qbh[t * KSP + o + 0] = h0;
            s.qbh[t * KSP + o + 1] = h1;
            s.qbh[t * KSP + o + 2] = h2;
            s.qbh[t * KSP + o + 3] = h3;
            s.qbl[t * KSP + o + 0] = __float2bfloat16_rn(q0 - __bfloat162float(h0));
            s.qbl[t * KSP + o + 1] = __float2bfloat16_rn(q1 - __bfloat162float(h1));
            s.qbl[t * KSP + o + 2] = __float2bfloat16_rn(q2f - __bfloat162float(h2));
            s.qbl[t * KSP + o + 3] = __float2bfloat16_rn(q3 - __bfloat162float(h3));
        }
        __syncthreads();

        float c0f[4] = {0.f, 0.f, 0.f, 0.f};
        float c1f[4] = {0.f, 0.f, 0.f, 0.f};
#pragma unroll
        for (int kt = 0; kt < 4; kt++) {
            int c0 = kt * 16 + kq;
            unsigned ahh[4], alo[4];
            ahh[0] = *(const unsigned*)&s.kh[r * KSP + c0];
            ahh[1] = *(const unsigned*)&s.kh[(r + 8) * KSP + c0];
            ahh[2] = *(const unsigned*)&s.kh[r * KSP + c0 + 8];
            ahh[3] = *(const unsigned*)&s.kh[(r + 8) * KSP + c0 + 8];
            alo[0] = *(const unsigned*)&s.kl[r * KSP + c0];
            alo[1] = *(const unsigned*)&s.kl[(r + 8) * KSP + c0];
            alo[2] = *(const unsigned*)&s.kl[r * KSP + c0 + 8];
            alo[3] = *(const unsigned*)&s.kl[(r + 8) * KSP + c0 + 8];
#pragma unroll
            for (int nf8 = 0; nf8 < 2; nf8++) {
                int n = nf8 * 8 + nl;
                unsigned bh[2], bl[2];
                bh[0] = *(const unsigned*)&s.qbh[n * KSP + c0];
                bh[1] = *(const unsigned*)&s.qbh[n * KSP + c0 + 8];
                bl[0] = *(const unsigned*)&s.qbl[n * KSP + c0];
                bl[1] = *(const unsigned*)&s.qbl[n * KSP + c0 + 8];
                float* cc = nf8 ? c1f : c0f;
                mma16816(cc, ahh, bh);
                mma16816(cc, alo, bh);
                mma16816(cc, ahh, bl);
            }
        }
        // write simS: cols of C are query indices t = nf8*8 + q2*2 + {0,1}
#pragma unroll
        for (int nf8 = 0; nf8 < 2; nf8++) {
            const float* cc = nf8 ? c1f : c0f;
            int t0 = nf8 * 8 + q2 * 2;
            s.simS[((t0 + 0) * 2 + h) * SIMP + r]     = cc[0];
            s.simS[((t0 + 1) * 2 + h) * SIMP + r]     = cc[1];
            s.simS[((t0 + 0) * 2 + h) * SIMP + r + 8] = cc[2];
            s.simS[((t0 + 1) * 2 + h) * SIMP + r + 8] = cc[3];
        }
        __syncthreads();   // also guards kh/kl restage for next head
    }

    // ---- per-query loop: logits only ----
    for (int t = 0; t < IT; t++) {
        const __nv_bfloat16* tq = s.ts_bf + t * 3 * PJ;
        unsigned tp0[3], tp1[3];
#pragma unroll
        for (int d = 0; d < 3; d++) {
            tp0[d] = (unsigned)*(const unsigned short*)(tq + d * PJ + r) * 0x10001u;
            tp1[d] = (unsigned)*(const unsigned short*)(tq + d * PJ + r + 8) * 0x10001u;
        }

        unsigned ah[16];
#pragma unroll
        for (int kt = 0; kt < 4; kt++) {
#pragma unroll
            for (int cp = 0; cp < 2; cp++) {
                uint4 W = s.w0p[kt * 8 + q2 + cp * 4];
                ah[kt * 4 + cp * 2 + 0] =
                    hmax2z(hfma2(tp0[0], W.x, hfma2(tp0[1], W.y, hfma2(tp0[2], W.z, W.w))));
                ah[kt * 4 + cp * 2 + 1] =
                    hmax2z(hfma2(tp1[0], W.x, hfma2(tp1[1], W.y, hfma2(tp1[2], W.z, W.w))));
            }
        }

        float acc2a[4] = {0.f, 0.f, 0.f, 0.f};
        float acc2b[4] = {0.f, 0.f, 0.f, 0.f};
#pragma unroll
        for (int kt2 = 0; kt2 < 4; kt2++) {
            float accA[4] = {0.f, 0.f, 0.f, 0.f};
            float accB[4] = {0.f, 0.f, 0.f, 0.f};
#pragma unroll
            for (int kt = 0; kt < 4; kt++) {
                mma16816(accA, &ah[kt * 4], bfr[2 * kt2][kt]);
                mma16816(accB, &ah[kt * 4], bfr[2 * kt2 + 1][kt]);
            }
            unsigned a2[4];
            a2[0] = hmax2z(hadd2(packcvt(accA[0], accA[1]), b1p[kt2][0]));
            a2[1] = hmax2z(hadd2(packcvt(accA[2], accA[3]), b1p[kt2][0]));
            a2[2] = hmax2z(hadd2(packcvt(accB[0], accB[1]), b1p[kt2][1]));
            a2[3] = hmax2z(hadd2(packcvt(accB[2], accB[3]), b1p[kt2][1]));
            mma16816((kt2 < 2) ? acc2a : acc2b, a2, bw2[kt2]);
        }

        if (q2 == 0) {
            s.attns[(t * 2 + 0) * PJ + r]     = s.simS[(t * 2 + 0) * SIMP + r] + acc2a[0] + acc2b[0];
            s.attns[(t * 2 + 1) * PJ + r]     = s.simS[(t * 2 + 1) * SIMP + r] + acc2a[1] + acc2b[1];
            s.attns[(t * 2 + 0) * PJ + r + 8] = s.simS[(t * 2 + 0) * SIMP + r + 8] + acc2a[2] + acc2b[2];
            s.attns[(t * 2 + 1) * PJ + r + 8] = s.simS[(t * 2 + 1) * SIMP + r + 8] + acc2a[3] + acc2b[3];
        }
    }
    __syncthreads();

    // ---- batched exp + row sums ----
    {
        int grp = tid >> 3;
        int l8 = tid & 7;
        float4* ar = (float4*)(s.attns + grp * PJ) + l8 * 4;
        float ps = 0.f;
#pragma unroll
        for (int kk = 0; kk < 4; kk++) {
            float4 a = ar[kk];
            a.x = __expf(a.x); a.y = __expf(a.y);
            a.z = __expf(a.z); a.w = __expf(a.w);
            ar[kk] = a;
            ps += (a.x + a.y) + (a.z + a.w);
        }
        ps += __shfl_xor_sync(0xffffffffu, ps, 1);
        ps += __shfl_xor_sync(0xffffffffu, ps, 2);
        ps += __shfl_xor_sync(0xffffffffu, ps, 4);
        if (l8 == 0) s.sumS[grp] = ps;
    }
    __syncthreads();

    // ---- attn @ V, loop-swapped (V row loaded once) ----
    {
        const int o = tid & 127, qh = tid >> 7, e = o >> 6;
        const ulonglong2* vrow = (const ulonglong2*)(g_v + (size_t)(bg * OFFD + o) * PJ);
        unsigned long long acc[8][2];
#pragma unroll
        for (int ti = 0; ti < 8; ti++) { acc[ti][0] = 0ull; acc[ti][1] = 0ull; }
#pragma unroll 4
        for (int q = 0; q < 32; q++) {
            ulonglong2 vv = vrow[q];
#pragma unroll
            for (int ti = 0; ti < 8; ti++) {
                int t = qh * 8 + ti;
                ulonglong2 av = *(const ulonglong2*)(s.attns + (t * 2 + e) * PJ + q * 4);
                acc[ti][0] = ffma2(av.x, vv.x, acc[ti][0]);
                acc[ti][1] = ffma2(av.y, vv.y, acc[ti][1]);
            }
        }
#pragma unroll
        for (int ti = 0; ti < 8; ti++) {
            int t = qh * 8 + ti;
            float S = s.sumS[t * 2 + e];
            float2 fa = unpack2(acc[ti][0]), fb = unpack2(acc[ti][1]);
            g_att[(size_t)(b * INNER + g * OFFD + o) * PQ + i0 + t] =
                (fa.x + fa.y + fb.x + fb.y) / S;
        }
    }
}

// ============================================================
// Kernel E: output projection
// ============================================================
__global__ void k_oproj(const float* __restrict__ wo, const float* __restrict__ bo,
                        float* __restrict__ out) {
    const int p0 = blockIdx.x * 64;
    const int o0 = blockIdx.y * 64;
    const int b = blockIdx.z;
    const int tid = threadIdx.x;
    const int tx = tid & 15, ty = tid >> 4;

    __shared__ __align__(16) float As[16 * 65];
    __shared__ __align__(16) float Bs[16 * 64];

    unsigned long long acc2[4][2];
#pragma unroll
    for (int a = 0; a < 4; a++) { acc2[a][0] = 0ull; acc2[a][1] = 0ull; }

    for (int k0 = 0; k0 < INNER; k0 += 16) {
        {
            int m = tid >> 2, kqq = (tid & 3) * 4;
            float4 wv = *(const float4*)(wo + (size_t)(o0 + m) * INNER + k0 + kqq);
            As[(kqq + 0) * 65 + m] = wv.x;
            As[(kqq + 1) * 65 + m] = wv.y;
            As[(kqq + 2) * 65 + m] = wv.z;
            As[(kqq + 3) * 65 + m] = wv.w;
            int k = tid >> 4, pq = (tid & 15) * 4;
            float4 bv = *(const float4*)(g_att + (size_t)(b * INNER + k0 + k) * PQ + p0 + pq);
            *(float4*)(Bs + k * 64 + pq) = bv;
        }
        __syncthreads();
#pragma unroll
        for (int k = 0; k < 16; k++) {
            const float* am = As + k * 65 + ty * 4;
            float a0f = am[0], a1f = am[1], a2f = am[2], a3f = am[3];
            const unsigned long long* bn =
                (const unsigned long long*)(Bs + k * 64 + tx * 4);
            unsigned long long b0 = bn[0], b1 = bn[1];
            unsigned long long a0 = pack2(a0f, a0f);
            unsigned long long a1 = pack2(a1f, a1f);
            unsigned long long a2 = pack2(a2f, a2f);
            unsigned long long a3 = pack2(a3f, a3f);
            acc2[0][0] = ffma2(a0, b0, acc2[0][0]); acc2[0][1] = ffma2(a0, b1, acc2[0][1]);
            acc2[1][0] = ffma2(a1, b0, acc2[1][0]); acc2[1][1] = ffma2(a1, b1, acc2[1][1]);
            acc2[2][0] = ffma2(a2, b0, acc2[2][0]); acc2[2][1] = ffma2(a2, b1, acc2[2][1]);
            acc2[3][0] = ffma2(a3, b0, acc2[3][0]); acc2[3][1] = ffma2(a3, b1, acc2[3][1]);
        }
        __syncthreads();
    }
#pragma unroll
    for (int a = 0; a < 4; a++) {
        float bias = bo[o0 + ty * 4 + a];
        float2 c0 = unpack2(acc2[a][0]);
        float2 c1 = unpack2(acc2[a][1]);
        float* op = out + (size_t)(b * DIMC + o0 + ty * 4 + a) * PQ + p0 + tx * 4;
        op[0] = c0.x + bias;
        op[1] = c0.y + bias;
        op[2] = c1.x + bias;
        op[3] = c1.y + bias;
    }
}

// ============================================================
extern "C" void kernel_launch(void* const* d_in, const int* in_sizes, int n_in,
                              void* d_out, int out_size) {
    const float* x    = (const float*)d_in[0];
    const float* wq   = (const float*)d_in[1];
    const float* wk   = (const float*)d_in[2];
    const float* wv   = (const float*)d_in[3];
    const float* dww  = (const float*)d_in[4];
    const float* dwb  = (const float*)d_in[5];
    const float* pww  = (const float*)d_in[6];
    const float* cw0  = (const float*)d_in[7];
    const float* cb0  = (const float*)d_in[8];
    const float* cw1  = (const float*)d_in[9];
    const float* cb1  = (const float*)d_in[10];
    const float* cw2  = (const float*)d_in[11];
    const float* cb2  = (const float*)d_in[12];
    const float* wo   = (const float*)d_in[13];
    const float* bo   = (const float*)d_in[14];
    float* out = (float*)d_out;
    (void)cb2; // per-head constant bias cancels in softmax

    cudaFuncSetAttribute(k_attn, cudaFuncAttributeMaxDynamicSharedMemorySize,
                         (int)sizeof(SmemD));

    k_qproj<<<dim3(PQ / 16, NBG), 128>>>(x, wq);
    k_offsets<<<dim3(8, NBG), 256>>>(dww, dwb, pww);
    k_sample_kv<<<dim3(NBG, PJ / 16), 256>>>(x, wk, wv);
    k_attn<<<dim3(PQ / IT, NBG), 256, sizeof(SmemD)>>>(cw0, cb0, cw1, cb1, cw2, cb2);
    k_oproj<<<dim3(PQ / 64, DIMC / 64, BB), 256>>>(wo, bo, out);
}

// round 14
// speedup vs baseline: 1.8121x; 1.1174x over previous
#include <cuda_runtime.h>
#include <cuda_bf16.h>
#include <math.h>

// ---------------- problem constants ----------------
#define BB 2
#define DIMC 256
#define GG 4
#define CHG 64          // DIM/GROUPS
#define OFFD 128
#define NBG 8           // B*GROUPS
#define FF 4
#define HH 16
#define WW 16
#define PQ 1024         // F*H*W
#define PJ 128          // FD*HD*WD
#define CPB 64
#define INNER 512
#define IT 16           // queries per block in kernel D
#define KP 66           // padded K stride (halves) for w1 smem
#define KSP 72          // padded stride for kh/kl/qb bf16 tiles
#define SIMP 130        // padded float stride for simS
#define ATP 138         // padded float stride for attns (conflict-free B-frags; 8B-aligned rows)
#define WPAD 129        // padded float stride for staged weights

// ---------------- scratch ----------------
__device__ float g_qT[NBG * PQ * OFFD];              // [bg][p][c]
__device__ float g_grid[NBG * PJ * 3];
__device__ __nv_bfloat16 g_t_bf[NBG * 3 * 16 * PJ];  // sign-log table (bf16)
__device__ __nv_bfloat16 g_khT[NBG * PJ * OFFD];     // k hi, [bg][j][o]
__device__ __nv_bfloat16 g_klT[NBG * PJ * OFFD];     // k lo
__device__ __nv_bfloat16 g_vh[NBG * OFFD * PJ];      // v hi, [bg][o][j]
__device__ __nv_bfloat16 g_vl[NBG * OFFD * PJ];      // v lo
__device__ float g_att[BB * INNER * PQ];

// ---------------- helpers ----------------
__device__ __forceinline__ unsigned long long ffma2(unsigned long long a,
                                                    unsigned long long b,
                                                    unsigned long long c) {
    unsigned long long d;
    asm("fma.rn.f32x2 %0, %1, %2, %3;" : "=l"(d) : "l"(a), "l"(b), "l"(c));
    return d;
}
__device__ __forceinline__ unsigned long long pack2(float lo, float hi) {
    unsigned long long d;
    asm("mov.b64 %0, {%1, %2};" : "=l"(d) : "f"(lo), "f"(hi));
    return d;
}
__device__ __forceinline__ float2 unpack2(unsigned long long v) {
    float2 r;
    asm("mov.b64 {%0, %1}, %2;" : "=f"(r.x), "=f"(r.y) : "l"(v));
    return r;
}
__device__ __forceinline__ void mma16816(float* c, const unsigned* a, const unsigned* b) {
    asm volatile(
        "mma.sync.aligned.m16n8k16.row.col.f32.bf16.bf16.f32 "
        "{%0,%1,%2,%3}, {%4,%5,%6,%7}, {%8,%9}, {%0,%1,%2,%3};"
        : "+f"(c[0]), "+f"(c[1]), "+f"(c[2]), "+f"(c[3])
        : "r"(a[0]), "r"(a[1]), "r"(a[2]), "r"(a[3]), "r"(b[0]), "r"(b[1]));
}
__device__ __forceinline__ unsigned hfma2(unsigned a, unsigned b, unsigned c) {
    unsigned d;
    asm("fma.rn.bf16x2 %0, %1, %2, %3;" : "=r"(d) : "r"(a), "r"(b), "r"(c));
    return d;
}
__device__ __forceinline__ unsigned hadd2(unsigned a, unsigned b) {
    unsigned d;
    asm("add.rn.bf16x2 %0, %1, %2;" : "=r"(d) : "r"(a), "r"(b));
    return d;
}
__device__ __forceinline__ unsigned hmax2z(unsigned a) {
    unsigned d;
    asm("max.bf16x2 %0, %1, %2;" : "=r"(d) : "r"(a), "r"(0u));
    return d;
}
__device__ __forceinline__ unsigned packcvt(float lo, float hi) {
    unsigned d;
    asm("cvt.rn.bf16x2.f32 %0, %1, %2;" : "=r"(d) : "f"(hi), "f"(lo));
    return d;
}

// ============================================================
// Kernel A: grouped 1x1 conv -> q (transposed layout only)
// ============================================================
__global__ void k_qproj(const float* __restrict__ x, const float* __restrict__ wq) {
    const int bg = blockIdx.y;
    const int b = bg >> 2, g = bg & 3;
    const int p0 = blockIdx.x * 16;
    const int o = threadIdx.x;

    __shared__ __align__(16) float wqs[CHG * WPAD];
    __shared__ __align__(16) float xs[CHG * 16];

    const float* wqg = wq + (size_t)g * OFFD * CHG;
    for (int e = o; e < OFFD * CHG; e += 128) {
        int oo = e >> 6, i = e & 63;
        wqs[i * WPAD + oo] = wqg[e];
    }
    for (int e = o; e < CHG * 16; e += 128) {
        int i = e >> 4, p = e & 15;
        xs[e] = x[(size_t)(b * DIMC + g * CHG + i) * PQ + p0 + p];
    }
    __syncthreads();

    unsigned long long acc2[8];
#pragma unroll
    for (int q = 0; q < 8; q++) acc2[q] = 0ull;

#pragma unroll 8
    for (int i = 0; i < CHG; i++) {
        float wv0 = wqs[i * WPAD + o];
        unsigned long long wv = pack2(wv0, wv0);
        const unsigned long long* xr = (const unsigned long long*)(xs + i * 16);
#pragma unroll
        for (int q = 0; q < 8; q++) acc2[q] = ffma2(wv, xr[q], acc2[q]);
    }
    float* qtout = g_qT + ((size_t)bg * PQ + p0) * OFFD + o;
#pragma unroll
    for (int q = 0; q < 8; q++) {
        float2 f = unpack2(acc2[q]);
        qtout[(q * 2 + 0) * OFFD] = f.x;
        qtout[(q * 2 + 1) * OFFD] = f.y;
    }
}

// ============================================================
// Kernel B: offsets -> grid coords + bf16 sign-log table
// ============================================================
__global__ __launch_bounds__(256)
void k_offsets(const float* __restrict__ dww, const float* __restrict__ dwb,
               const float* __restrict__ pww) {
    const int jt = blockIdx.x;
    const int bg = blockIdx.y;
    const int tid = threadIdx.x;
    const int half = tid >> 7;
    const int c = tid & 127;
    const int lane = tid & 31;
    const int hw = (tid >> 5) & 3;

    __shared__ __align__(16) float dws[64 * WPAD];
    __shared__ __align__(16) float pws[3 * OFFD];
    __shared__ float dwbS[OFFD];
    __shared__ float acts[2][OFFD];
    __shared__ float sred[2][3];
    __shared__ float gcoord[2][3];

    for (int e = tid; e < 64 * OFFD; e += 256) {
        int cc = e >> 6, k = e & 63;
        dws[k * WPAD + cc] = dww[e];
    }
    for (int e = tid; e < 3 * OFFD; e += 256) pws[e] = pww[e];
    if (tid < OFFD) dwbS[tid] = dwb[tid];
    __syncthreads();

    const float* qT = g_qT + (size_t)bg * PQ * OFFD + c;

    for (int it = 0; it < 8; it++) {
        const int pos = jt * 16 + it * 2 + half;
        const int zo = pos >> 6;
        const int yo = (pos >> 3) & 7;
        const int xo = pos & 7;

        float acc = 0.f;
#pragma unroll
        for (int kz = 0; kz < 4; kz++) {
            int z = 2 * zo - 1 + kz;
            if (z < 0 || z >= FF) continue;
#pragma unroll
            for (int ky = 0; ky < 4; ky++) {
                int y = 2 * yo - 1 + ky;
                if (y < 0 || y >= HH) continue;
#pragma unroll
                for (int kx = 0; kx < 4; kx++) {
                    int xx = 2 * xo - 1 + kx;
                    if (xx < 0 || xx >= WW) continue;
                    int p = (z * HH + y) * WW + xx;
                    acc = fmaf(qT[(size_t)p * OFFD],
                               dws[((kz * 4 + ky) * 4 + kx) * WPAD + c], acc);
                }
            }
        }
        float v = acc + dwbS[c];
        acts[half][c] = 0.5f * v * (1.f + erff(v * 0.70710678118654752f));
        __syncthreads();

        if (hw < 3) {
            float s = 0.f;
#pragma unroll
            for (int q = 0; q < 4; q++) {
                int cc = lane + q * 32;
                s = fmaf(acts[half][cc], pws[hw * OFFD + cc], s);
            }
#pragma unroll
            for (int off = 16; off; off >>= 1)
                s += __shfl_xor_sync(0xffffffffu, s, off);
            if (lane == 0) sred[half][hw] = s;
        }
        __syncthreads();

        if (c < 3) {
            float off = tanhf(sred[half][c]) * 2.0f;
            int vo = (c == 0) ? zo : ((c == 1) ? yo : xo);
            float denom = (c == 0) ? 1.0f : 7.0f;
            float gcv = 2.0f * ((float)vo + off) / denom - 1.0f;
            gcoord[half][c] = gcv;
            g_grid[(size_t)(bg * PJ + pos) * 3 + c] = gcv;
        }
        __syncthreads();

        if (c < 36) {
            int d = (c < 4) ? 0 : ((c < 20) ? 1 : 2);
            int vq = (c < 4) ? c : ((c < 20) ? c - 4 : c - 20);
            float denom = (d == 0) ? 3.0f : 15.0f;
            float gq = 2.0f * (float)vq / denom - 1.0f;
            float p = gq - gcoord[half][d];
            g_t_bf[(((size_t)bg * 3 + d) * 16 + vq) * PJ + pos] =
                __float2bfloat16_rn(copysignf(log1pf(fabsf(p)), p));
        }
    }
}

// ============================================================
// Kernel C: trilinear grid-sample + k/v projections
// k -> hi/lo bf16 [bg][j][o]; v -> hi/lo bf16 [bg][o][j]
// ============================================================
__global__ __launch_bounds__(256)
void k_sample_kv(const float* __restrict__ x, const float* __restrict__ wk,
                 const float* __restrict__ wv) {
    const int bg = blockIdx.x;
    const int jt = blockIdx.y;
    const int b = bg >> 2, g = bg & 3;
    const int tid = threadIdx.x;

    __shared__ __align__(16) float wks[CHG * WPAD];
    __shared__ __align__(16) float wvs[CHG * WPAD];
    __shared__ __align__(16) float kvsS[16 * CHG];

    const float* wkg = wk + (size_t)g * OFFD * CHG;
    const float* wvg = wv + (size_t)g * OFFD * CHG;
    for (int e = tid; e < OFFD * CHG; e += 256) {
        int o = e >> 6, i = e & 63;
        wks[i * WPAD + o] = wkg[e];
        wvs[i * WPAD + o] = wvg[e];
    }

#pragma unroll
    for (int pass = 0; pass < 4; pass++) {
        int jl = pass * 4 + (tid >> 6);
        int ch = tid & 63;
        int j = jt * 16 + jl;
        const float* gp = g_grid + (size_t)(bg * PJ + j) * 3;
        float g0 = gp[0], g1 = gp[1], g2 = gp[2];
        float ix = ((g0 + 1.f) * (float)WW - 1.f) * 0.5f;
        float iy = ((g1 + 1.f) * (float)HH - 1.f) * 0.5f;
        float iz = ((g2 + 1.f) * (float)FF - 1.f) * 0.5f;
        float fx0 = floorf(ix), fy0 = floorf(iy), fz0 = floorf(iz);
        float tx = ix - fx0, ty = iy - fy0, tz = iz - fz0;
        int x0 = (int)fx0, y0 = (int)fy0, z0 = (int)fz0;

        const float* xp = x + (size_t)(b * DIMC + g * CHG + ch) * PQ;
        float acc = 0.f;
#pragma unroll
        for (int dz = 0; dz < 2; dz++)
#pragma unroll
            for (int dy = 0; dy < 2; dy++)
#pragma unroll
                for (int dx = 0; dx < 2; dx++) {
                    int xc = x0 + dx, yc = y0 + dy, zc = z0 + dz;
                    float wgt = (dx ? tx : 1.f - tx) * (dy ? ty : 1.f - ty) *
                                (dz ? tz : 1.f - tz);
                    bool valid = (xc >= 0) & (xc < WW) & (yc >= 0) & (yc < HH) &
                                 (zc >= 0) & (zc < FF);
                    int xi = min(max(xc, 0), WW - 1);
                    int yi = min(max(yc, 0), HH - 1);
                    int zi = min(max(zc, 0), FF - 1);
                    float val = xp[(zi * HH + yi) * WW + xi];
                    acc += valid ? val * wgt : 0.f;
                }
        kvsS[jl * CHG + ch] = acc;
    }
    __syncthreads();

    const int o = tid & 127;
    const int sel = tid >> 7;
    const float* ws = sel ? wvs : wks;

    float acc[16];
#pragma unroll
    for (int jl = 0; jl < 16; jl++) acc[jl] = 0.f;
#pragma unroll 8
    for (int i = 0; i < CHG; i++) {
        float wv0 = ws[i * WPAD + o];
#pragma unroll
        for (int jl = 0; jl < 16; jl++)
            acc[jl] = fmaf(wv0, kvsS[jl * CHG + i], acc[jl]);
    }
    if (sel) {
        unsigned hiw[8], low[8];
#pragma unroll
        for (int kk = 0; kk < 8; kk++) {
            float v0 = acc[kk * 2], v1 = acc[kk * 2 + 1];
            unsigned hw = packcvt(v0, v1);
            __nv_bfloat162 hv = *(__nv_bfloat162*)&hw;
            hiw[kk] = hw;
            low[kk] = packcvt(v0 - __bfloat162float(hv.x), v1 - __bfloat162float(hv.y));
        }
        size_t base = ((size_t)(bg * OFFD + o)) * PJ + jt * 16;
        ((uint4*)(g_vh + base))[0] = make_uint4(hiw[0], hiw[1], hiw[2], hiw[3]);
        ((uint4*)(g_vh + base))[1] = make_uint4(hiw[4], hiw[5], hiw[6], hiw[7]);
        ((uint4*)(g_vl + base))[0] = make_uint4(low[0], low[1], low[2], low[3]);
        ((uint4*)(g_vl + base))[1] = make_uint4(low[4], low[5], low[6], low[7]);
    } else {
#pragma unroll
        for (int jl = 0; jl < 16; jl++) {
            float ak = acc[jl];
            __nv_bfloat16 hi = __float2bfloat16_rn(ak);
            __nv_bfloat16 lo = __float2bfloat16_rn(ak - __bfloat162float(hi));
            size_t idx = ((size_t)bg * PJ + jt * 16 + jl) * OFFD + o;
            g_khT[idx] = hi;
            g_klT[idx] = lo;
        }
    }
}

// ============================================================
// Kernel D v11b: sim MMA + query-loop + attn@V via 3-term MMA
// (exp pass uses 8-byte accesses: ATP rows are 8B- but not 16B-aligned)
// ============================================================
struct __align__(16) SmemD {
    __nv_bfloat16 w1h[CPB * KP];
    __nv_bfloat16 kh[PJ * KSP];
    __nv_bfloat16 kl[PJ * KSP];
    __nv_bfloat16 qbh[16 * KSP];
    __nv_bfloat16 qbl[16 * KSP];
    __nv_bfloat16 ts_bf[IT * 3 * PJ];
    float attns[IT * 2 * ATP];     // f32 logits, then in-place hi/lo bf16
    float simS[IT * 2 * SIMP];
    uint4 w0p[32];
    float w2s[CPB * 2];
    float b1s[CPB];
    float sumS[IT * 2];
};

__global__ __launch_bounds__(256, 2)
void k_attn(const float* __restrict__ cw0, const float* __restrict__ cb0,
            const float* __restrict__ cw1, const float* __restrict__ cb1,
            const float* __restrict__ cw2, const float* __restrict__ cb2) {
    extern __shared__ SmemD smD[];
    SmemD& s = smD[0];

    const int bg = blockIdx.y;
    const int b = bg >> 2, g = bg & 3;
    const int i0 = blockIdx.x * IT;
    const int tid = threadIdx.x;
    const int lane = tid & 31, w = tid >> 5;

    // ---- stage block-invariant tables ----
    for (int e = tid; e < CPB * CPB; e += 256) {
        int k = e >> 6, n = e & 63;
        s.w1h[n * KP + k] = __float2bfloat16_rn(cw1[e]);
    }
    if (tid < 32) {
        int c = tid * 2;
        uint4 wp;
        wp.x = packcvt(cw0[c], cw0[c + 1]);
        wp.y = packcvt(cw0[64 + c], cw0[64 + c + 1]);
        wp.z = packcvt(cw0[128 + c], cw0[128 + c + 1]);
        wp.w = packcvt(cb0[c], cb0[c + 1]);
        s.w0p[tid] = wp;
    }
    if (tid >= 64 && tid < 192) s.w2s[tid - 64] = cw2[tid - 64];
    if (tid >= 192) s.b1s[tid - 192] = cb1[tid - 192];
    for (int e = tid; e < 768; e += 256) {
        int row = e >> 4, seg = e & 15;
        int q = row / 3, d = row - q * 3;
        int i = i0 + q;
        int vq = (d == 0) ? (i >> 8) : ((d == 1) ? ((i >> 4) & 15) : (i & 15));
        *(uint4*)&s.ts_bf[row * PJ + seg * 8] =
            *(const uint4*)&g_t_bf[(((size_t)bg * 3 + d) * 16 + vq) * PJ + seg * 8];
    }
    __syncthreads();                                     // barrier 1

    const int r = w * 16 + (lane >> 2);
    const int q2 = lane & 3;
    const int kq = q2 * 2;
    const int nl = lane >> 2;

    // ---- hoist w1 B-fragments into registers ----
    unsigned bfr[8][4][2];
#pragma unroll
    for (int nf = 0; nf < 8; nf++) {
        int nrow = nf * 8 + nl;
#pragma unroll
        for (int kt = 0; kt < 4; kt++) {
            bfr[nf][kt][0] = *(const unsigned*)&s.w1h[nrow * KP + kt * 16 + kq];
            bfr[nf][kt][1] = *(const unsigned*)&s.w1h[nrow * KP + kt * 16 + kq + 8];
        }
    }
    unsigned bw2[4][2], b1p[4][2];
#pragma unroll
    for (int kt2 = 0; kt2 < 4; kt2++) {
        int k0 = kt2 * 16 + kq;
        bw2[kt2][0] = (nl < 2) ? packcvt(s.w2s[k0 * 2 + nl], s.w2s[(k0 + 1) * 2 + nl]) : 0u;
        bw2[kt2][1] = (nl < 2) ? packcvt(s.w2s[(k0 + 8) * 2 + nl], s.w2s[(k0 + 9) * 2 + nl]) : 0u;
        b1p[kt2][0] = packcvt(s.b1s[k0], s.b1s[k0 + 1]);
        b1p[kt2][1] = packcvt(s.b1s[k0 + 8], s.b1s[k0 + 9]);
    }

    // ---- sim via MMA: per head ----
    for (int h = 0; h < 2; h++) {
        for (int e = tid; e < 1024; e += 256) {
            int row = e >> 3, seg = e & 7;
            size_t src = ((size_t)bg * PJ + row) * OFFD + h * 64 + seg * 8;
            *(uint4*)&s.kh[row * KSP + seg * 8] = *(const uint4*)&g_khT[src];
            *(uint4*)&s.kl[row * KSP + seg * 8] = *(const uint4*)&g_klT[src];
        }
        {
            int base = tid * 4;
            int t = base >> 6, o = base & 63;
            float4 qv = *(const float4*)&g_qT[((size_t)bg * PQ + i0 + t) * OFFD + h * 64 + o];
            float q0 = qv.x * 0.125f, q1 = qv.y * 0.125f,
                  q2f = qv.z * 0.125f, q3 = qv.w * 0.125f;
            __nv_bfloat16 h0 = __float2bfloat16_rn(q0);
            __nv_bfloat16 h1 = __float2bfloat16_rn(q1);
            __nv_bfloat16 h2 = __float2bfloat16_rn(q2f);
            __nv_bfloat16 h3 = __float2bfloat16_rn(q3);
            s.qbh[t * KSP + o + 0] = h0;
            s.qbh[t * KSP + o + 1] = h1;
            s.qbh[t * KSP + o + 2] = h2;
            s.qbh[t * KSP + o + 3] = h3;
            s.qbl[t * KSP + o + 0] = __float2bfloat16_rn(q0 - __bfloat162float(h0));
            s.qbl[t * KSP + o + 1] = __float2bfloat16_rn(q1 - __bfloat162float(h1));
            s.qbl[t * KSP + o + 2] = __float2bfloat16_rn(q2f - __bfloat162float(h2));
            s.qbl[t * KSP + o + 3] = __float2bfloat16_rn(q3 - __bfloat162float(h3));
        }
        __syncthreads();

        float c0f[4] = {0.f, 0.f, 0.f, 0.f};
        float c1f[4] = {0.f, 0.f, 0.f, 0.f};
#pragma unroll
        for (int kt = 0; kt < 4; kt++) {
            int c0 = kt * 16 + kq;
            unsigned ahh[4], alo[4];
            ahh[0] = *(const unsigned*)&s.kh[r * KSP + c0];
            ahh[1] = *(const unsigned*)&s.kh[(r + 8) * KSP + c0];
            ahh[2] = *(const unsigned*)&s.kh[r * KSP + c0 + 8];
            ahh[3] = *(const unsigned*)&s.kh[(r + 8) * KSP + c0 + 8];
            alo[0] = *(const unsigned*)&s.kl[r * KSP + c0];
            alo[1] = *(const unsigned*)&s.kl[(r + 8) * KSP + c0];
            alo[2] = *(const unsigned*)&s.kl[r * KSP + c0 + 8];
            alo[3] = *(const unsigned*)&s.kl[(r + 8) * KSP + c0 + 8];
#pragma unroll
            for (int nf8 = 0; nf8 < 2; nf8++) {
                int n = nf8 * 8 + nl;
                unsigned bh[2], bl[2];
                bh[0] = *(const unsigned*)&s.qbh[n * KSP + c0];
                bh[1] = *(const unsigned*)&s.qbh[n * KSP + c0 + 8];
                bl[0] = *(const unsigned*)&s.qbl[n * KSP + c0];
                bl[1] = *(const unsigned*)&s.qbl[n * KSP + c0 + 8];
                float* cc = nf8 ? c1f : c0f;
                mma16816(cc, ahh, bh);
                mma16816(cc, alo, bh);
                mma16816(cc, ahh, bl);
            }
        }
#pragma unroll
        for (int nf8 = 0; nf8 < 2; nf8++) {
            const float* cc = nf8 ? c1f : c0f;
            int t0 = nf8 * 8 + q2 * 2;
            s.simS[((t0 + 0) * 2 + h) * SIMP + r]     = cc[0];
            s.simS[((t0 + 1) * 2 + h) * SIMP + r]     = cc[1];
            s.simS[((t0 + 0) * 2 + h) * SIMP + r + 8] = cc[2];
            s.simS[((t0 + 1) * 2 + h) * SIMP + r + 8] = cc[3];
        }
        __syncthreads();
    }

    // ---- per-query loop: logits only ----
    for (int t = 0; t < IT; t++) {
        const __nv_bfloat16* tq = s.ts_bf + t * 3 * PJ;
        unsigned tp0[3], tp1[3];
#pragma unroll
        for (int d = 0; d < 3; d++) {
            tp0[d] = (unsigned)*(const unsigned short*)(tq + d * PJ + r) * 0x10001u;
            tp1[d] = (unsigned)*(const unsigned short*)(tq + d * PJ + r + 8) * 0x10001u;
        }

        unsigned ah[16];
#pragma unroll
        for (int kt = 0; kt < 4; kt++) {
#pragma unroll
            for (int cp = 0; cp < 2; cp++) {
                uint4 W = s.w0p[kt * 8 + q2 + cp * 4];
                ah[kt * 4 + cp * 2 + 0] =
                    hmax2z(hfma2(tp0[0], W.x, hfma2(tp0[1], W.y, hfma2(tp0[2], W.z, W.w))));
                ah[kt * 4 + cp * 2 + 1] =
                    hmax2z(hfma2(tp1[0], W.x, hfma2(tp1[1], W.y, hfma2(tp1[2], W.z, W.w))));
            }
        }

        float acc2a[4] = {0.f, 0.f, 0.f, 0.f};
        float acc2b[4] = {0.f, 0.f, 0.f, 0.f};
#pragma unroll
        for (int kt2 = 0; kt2 < 4; kt2++) {
            float accA[4] = {0.f, 0.f, 0.f, 0.f};
            float accB[4] = {0.f, 0.f, 0.f, 0.f};
#pragma unroll
            for (int kt = 0; kt < 4; kt++) {
                mma16816(accA, &ah[kt * 4], bfr[2 * kt2][kt]);
                mma16816(accB, &ah[kt * 4], bfr[2 * kt2 + 1][kt]);
            }
            unsigned a2[4];
            a2[0] = hmax2z(hadd2(packcvt(accA[0], accA[1]), b1p[kt2][0]));
            a2[1] = hmax2z(hadd2(packcvt(accA[2], accA[3]), b1p[kt2][0]));
            a2[2] = hmax2z(hadd2(packcvt(accB[0], accB[1]), b1p[kt2][1]));
            a2[3] = hmax2z(hadd2(packcvt(accB[2], accB[3]), b1p[kt2][1]));
            mma16816((kt2 < 2) ? acc2a : acc2b, a2, bw2[kt2]);
        }

        if (q2 == 0) {
            s.attns[(t * 2 + 0) * ATP + r]     = s.simS[(t * 2 + 0) * SIMP + r] + acc2a[0] + acc2b[0];
            s.attns[(t * 2 + 1) * ATP + r]     = s.simS[(t * 2 + 1) * SIMP + r] + acc2a[1] + acc2b[1];
            s.attns[(t * 2 + 0) * ATP + r + 8] = s.simS[(t * 2 + 0) * SIMP + r + 8] + acc2a[2] + acc2b[2];
            s.attns[(t * 2 + 1) * ATP + r + 8] = s.simS[(t * 2 + 1) * SIMP + r + 8] + acc2a[3] + acc2b[3];
        }
    }
    __syncthreads();                                     // barrier: logits done

    // ---- batched exp + in-place hi/lo split + row sums (8B accesses) ----
    {
        int grp = tid >> 3;            // row = t*2 + head
        int l8 = tid & 7;
        float* rowp = s.attns + grp * ATP;
        float vals[16];
#pragma unroll
        for (int kk = 0; kk < 8; kk++) {
            float2 a = *(float2*)(rowp + l8 * 16 + kk * 2);
            vals[kk * 2 + 0] = __expf(a.x);
            vals[kk * 2 + 1] = __expf(a.y);
        }
        float ps = 0.f;
        unsigned hiw[8], low[8];
#pragma unroll
        for (int kk = 0; kk < 8; kk++) {
            float v0 = vals[kk * 2], v1 = vals[kk * 2 + 1];
            ps += v0 + v1;
            unsigned hw = packcvt(v0, v1);
            __nv_bfloat162 hv = *(__nv_bfloat162*)&hw;
            hiw[kk] = hw;
            low[kk] = packcvt(v0 - __bfloat162float(hv.x), v1 - __bfloat162float(hv.y));
        }
        __syncwarp();
        // hi at halfwords [0,128), lo at halfwords [128,256) within the row
        char* rb = (char*)rowp;
        *(uint2*)(rb + l8 * 32 + 0)  = make_uint2(hiw[0], hiw[1]);
        *(uint2*)(rb + l8 * 32 + 8)  = make_uint2(hiw[2], hiw[3]);
        *(uint2*)(rb + l8 * 32 + 16) = make_uint2(hiw[4], hiw[5]);
        *(uint2*)(rb + l8 * 32 + 24) = make_uint2(hiw[6], hiw[7]);
        *(uint2*)(rb + 256 + l8 * 32 + 0)  = make_uint2(low[0], low[1]);
        *(uint2*)(rb + 256 + l8 * 32 + 8)  = make_uint2(low[2], low[3]);
        *(uint2*)(rb + 256 + l8 * 32 + 16) = make_uint2(low[4], low[5]);
        *(uint2*)(rb + 256 + l8 * 32 + 24) = make_uint2(low[6], low[7]);
        ps += __shfl_xor_sync(0xffffffffu, ps, 1);
        ps += __shfl_xor_sync(0xffffffffu, ps, 2);
        ps += __shfl_xor_sync(0xffffffffu, ps, 4);
        if (l8 == 0) s.sumS[grp] = ps;
    }
    __syncthreads();                                     // barrier: attn ready

    // ---- attn @ V via 3-term MMA: warp = (head, m-tile) ----
    {
        const int e = w >> 2, mt = w & 3;
        const int o = e * 64 + mt * 16 + nl;             // A row (and o+8)
        float cc[2][4];
#pragma unroll
        for (int nf8 = 0; nf8 < 2; nf8++)
#pragma unroll
            for (int q = 0; q < 4; q++) cc[nf8][q] = 0.f;

#pragma unroll
        for (int kt = 0; kt < 8; kt++) {
            size_t base = ((size_t)(bg * OFFD + o)) * PJ + kt * 16 + kq;
            unsigned ahh[4], alo[4];
            ahh[0] = *(const unsigned*)(g_vh + base);
            ahh[1] = *(const unsigned*)(g_vh + base + 8 * PJ);
            ahh[2] = *(const unsigned*)(g_vh + base + 8);
            ahh[3] = *(const unsigned*)(g_vh + base + 8 * PJ + 8);
            alo[0] = *(const unsigned*)(g_vl + base);
            alo[1] = *(const unsigned*)(g_vl + base + 8 * PJ);
            alo[2] = *(const unsigned*)(g_vl + base + 8);
            alo[3] = *(const unsigned*)(g_vl + base + 8 * PJ + 8);
#pragma unroll
            for (int nf8 = 0; nf8 < 2; nf8++) {
                int row = (nf8 * 8 + nl) * 2 + e;
                const unsigned short* hrow = (const unsigned short*)(s.attns + row * ATP);
                unsigned bh[2], bl[2];
                bh[0] = *(const unsigned*)(hrow + kt * 16 + kq);
                bh[1] = *(const unsigned*)(hrow + kt * 16 + kq + 8);
                bl[0] = *(const unsigned*)(hrow + 128 + kt * 16 + kq);
                bl[1] = *(const unsigned*)(hrow + 128 + kt * 16 + kq + 8);
                mma16816(cc[nf8], ahh, bh);
                mma16816(cc[nf8], alo, bh);
                mma16816(cc[nf8], ahh, bl);
            }
        }
#pragma unroll
        for (int nf8 = 0; nf8 < 2; nf8++) {
            int t0 = nf8 * 8 + kq;
            float S0 = s.sumS[(t0 + 0) * 2 + e];
            float S1 = s.sumS[(t0 + 1) * 2 + e];
            float* op = g_att + ((size_t)(b * INNER + g * OFFD + o)) * PQ + i0 + t0;
            *(float2*)op = make_float2(cc[nf8][0] / S0, cc[nf8][1] / S1);
            *(float2*)(op + 8 * PQ) = make_float2(cc[nf8][2] / S0, cc[nf8][3] / S1);
        }
    }
}

// ============================================================
// Kernel E: output projection
// ============================================================
__global__ void k_oproj(const float* __restrict__ wo, const float* __restrict__ bo,
                        float* __restrict__ out) {
    const int p0 = blockIdx.x * 64;
    const int o0 = blockIdx.y * 64;
    const int b = blockIdx.z;
    const int tid = threadIdx.x;
    const int tx = tid & 15, ty = tid >> 4;

    __shared__ __align__(16) float As[16 * 65];
    __shared__ __align__(16) float Bs[16 * 64];

    unsigned long long acc2[4][2];
#pragma unroll
    for (int a = 0; a < 4; a++) { acc2[a][0] = 0ull; acc2[a][1] = 0ull; }

    for (int k0 = 0; k0 < INNER; k0 += 16) {
        {
            int m = tid >> 2, kqq = (tid & 3) * 4;
            float4 wv = *(const float4*)(wo + (size_t)(o0 + m) * INNER + k0 + kqq);
            As[(kqq + 0) * 65 + m] = wv.x;
            As[(kqq + 1) * 65 + m] = wv.y;
            As[(kqq + 2) * 65 + m] = wv.z;
            As[(kqq + 3) * 65 + m] = wv.w;
            int k = tid >> 4, pq = (tid & 15) * 4;
            float4 bv = *(const float4*)(g_att + (size_t)(b * INNER + k0 + k) * PQ + p0 + pq);
            *(float4*)(Bs + k * 64 + pq) = bv;
        }
        __syncthreads();
#pragma unroll
        for (int k = 0; k < 16; k++) {
            const float* am = As + k * 65 + ty * 4;
            float a0f = am[0], a1f = am[1], a2f = am[2], a3f = am[3];
            const unsigned long long* bn =
                (const unsigned long long*)(Bs + k * 64 + tx * 4);
            unsigned long long b0 = bn[0], b1 = bn[1];
            unsigned long long a0 = pack2(a0f, a0f);
            unsigned long long a1 = pack2(a1f, a1f);
            unsigned long long a2 = pack2(a2f, a2f);
            unsigned long long a3 = pack2(a3f, a3f);
            acc2[0][0] = ffma2(a0, b0, acc2[0][0]); acc2[0][1] = ffma2(a0, b1, acc2[0][1]);
            acc2[1][0] = ffma2(a1, b0, acc2[1][0]); acc2[1][1] = ffma2(a1, b1, acc2[1][1]);
            acc2[2][0] = ffma2(a2, b0, acc2[2][0]); acc2[2][1] = ffma2(a2, b1, acc2[2][1]);
            acc2[3][0] = ffma2(a3, b0, acc2[3][0]); acc2[3][1] = ffma2(a3, b1, acc2[3][1]);
        }
        __syncthreads();
    }
#pragma unroll
    for (int a = 0; a < 4; a++) {
        float bias = bo[o0 + ty * 4 + a];
        float2 c0 = unpack2(acc2[a][0]);
        float2 c1 = unpack2(acc2[a][1]);
        float* op = out + (size_t)(b * DIMC + o0 + ty * 4 + a) * PQ + p0 + tx * 4;
        op[0] = c0.x + bias;
        op[1] = c0.y + bias;
        op[2] = c1.x + bias;
        op[3] = c1.y + bias;
    }
}

// ============================================================
extern "C" void kernel_launch(void* const* d_in, const int* in_sizes, int n_in,
                              void* d_out, int out_size) {
    const float* x    = (const float*)d_in[0];
    const float* wq   = (const float*)d_in[1];
    const float* wk   = (const float*)d_in[2];
    const float* wv   = (const float*)d_in[3];
    const float* dww  = (const float*)d_in[4];
    const float* dwb  = (const float*)d_in[5];
    const float* pww  = (const float*)d_in[6];
    const float* cw0  = (const float*)d_in[7];
    const float* cb0  = (const float*)d_in[8];
    const float* cw1  = (const float*)d_in[9];
    const float* cb1  = (const float*)d_in[10];
    const float* cw2  = (const float*)d_in[11];
    const float* cb2  = (const float*)d_in[12];
    const float* wo   = (const float*)d_in[13];
    const float* bo   = (const float*)d_in[14];
    float* out = (float*)d_out;
    (void)cb2; // per-head constant bias cancels in softmax

    cudaFuncSetAttribute(k_attn, cudaFuncAttributeMaxDynamicSharedMemorySize,
                         (int)sizeof(SmemD));

    k_qproj<<<dim3(PQ / 16, NBG), 128>>>(x, wq);
    k_offsets<<<dim3(8, NBG), 256>>>(dww, dwb, pww);
    k_sample_kv<<<dim3(NBG, PJ / 16), 256>>>(x, wk, wv);
    k_attn<<<dim3(PQ / IT, NBG), 256, sizeof(SmemD)>>>(cw0, cb0, cw1, cb1, cw2, cb2);
    k_oproj<<<dim3(PQ / 64, DIMC / 64, BB), 256>>>(wo, bo, out);
}